// round 3
// baseline (speedup 1.0000x reference)
#include <cuda_runtime.h>
#include <cstdint>
#include <cstddef>

#define NB   32
#define NN   512
#define NL   64
#define NC   64
#define NF   192

__device__ float g_T2[NN * NN];
__device__ float g_z[(size_t)NB * NF * NN * NL];   // [(b*192 + o*3 + k)][n][l]

// ---- packed fp32 helpers (FFMA2: 2 FMAs per fma-pipe slot) -----------------
__device__ __forceinline__ unsigned long long pack2(float a, float b) {
    unsigned long long r;
    asm("mov.b64 %0, {%1, %2};" : "=l"(r) : "f"(a), "f"(b));
    return r;
}
__device__ __forceinline__ void unpack2(unsigned long long v, float& lo, float& hi) {
    asm("mov.b64 {%0, %1}, %2;" : "=f"(lo), "=f"(hi) : "l"(v));
}
__device__ __forceinline__ void ffma2(unsigned long long& acc,
                                      unsigned long long a, unsigned long long b) {
    asm("fma.rn.f32x2 %0, %1, %2, %0;" : "+l"(acc) : "l"(a), "l"(b));
}

// ---------------------------------------------------------------------------
// K1: T2 = 2 * adj @ adj - I
// ---------------------------------------------------------------------------
__global__ void k1_T2(const float* __restrict__ adj) {
    __shared__ float As[16][16];
    __shared__ float Bs[16][17];
    const int tx = threadIdx.x, ty = threadIdx.y;
    const int q = blockIdx.y * 16 + ty;
    const int n = blockIdx.x * 16 + tx;
    float acc = 0.f;
    for (int t0 = 0; t0 < NN; t0 += 16) {
        As[ty][tx] = adj[(size_t)q * NN + t0 + tx];
        Bs[ty][tx] = adj[(size_t)(t0 + ty) * NN + n];
        __syncthreads();
#pragma unroll
        for (int j = 0; j < 16; j++) acc = fmaf(As[ty][j], Bs[j][tx], acc);
        __syncthreads();
    }
    g_T2[(size_t)q * NN + n] = 2.f * acc - (q == n ? 1.f : 0.f);
}

// ---------------------------------------------------------------------------
// K2: z[b][f][m] = sum_c Wr[f][c] * x[b][c][m]   (FFMA2 inner loop)
// ---------------------------------------------------------------------------
__global__ __launch_bounds__(256) void k2_mix(const float* __restrict__ x,
                                              const float* __restrict__ W) {
    __shared__ float Ws[64][64];   // [c][f_local]
    __shared__ float Xs[64][64];   // [c][m_local]
    const int b  = blockIdx.z;
    const int f0 = blockIdx.y * 64;
    const int m0 = blockIdx.x * 64;
    const int t  = threadIdx.x;

#pragma unroll
    for (int i = 0; i < 16; i++) {
        int e = t + i * 256;
        int c = e >> 6, fl = e & 63;
        int f = f0 + fl;
        Ws[c][fl] = W[(f / 3) * NF + c * 3 + (f % 3)];
    }
#pragma unroll
    for (int i = 0; i < 4; i++) {
        int e = t + i * 256;
        int c = e >> 4, mv = e & 15;
        const float* src = x + ((size_t)(b * NC + c)) * 32768 + m0;
        *(float4*)&Xs[c][mv * 4] = ((const float4*)src)[mv];
    }
    __syncthreads();

    const int tm = t & 15, tf = t >> 4;
    unsigned long long acc2[4][2];
#pragma unroll
    for (int i = 0; i < 4; i++) {
        acc2[i][0] = pack2(0.f, 0.f);
        acc2[i][1] = pack2(0.f, 0.f);
    }

#pragma unroll
    for (int c = 0; c < 64; c++) {
        float4 a = *(const float4*)&Ws[c][tf * 4];
        ulonglong2 bp = *(const ulonglong2*)&Xs[c][tm * 4];
        unsigned long long ap[4] = {pack2(a.x, a.x), pack2(a.y, a.y),
                                    pack2(a.z, a.z), pack2(a.w, a.w)};
#pragma unroll
        for (int i = 0; i < 4; i++) {
            ffma2(acc2[i][0], ap[i], bp.x);
            ffma2(acc2[i][1], ap[i], bp.y);
        }
    }

#pragma unroll
    for (int i = 0; i < 4; i++) {
        int f = f0 + tf * 4 + i;
        float4 v;
        unpack2(acc2[i][0], v.x, v.y);
        unpack2(acc2[i][1], v.z, v.w);
        *(float4*)&g_z[((size_t)b * NF + f) * 32768 + m0 + tm * 4] = v;
    }
}

// ---------------------------------------------------------------------------
// K3: spatial contraction, FFMA2 inner loop (8x8 tile -> 8x4 packed acc)
// ---------------------------------------------------------------------------
__global__ __launch_bounds__(256) void k3_main(const float* __restrict__ ds,
                                               const float* __restrict__ adj,
                                               const float* __restrict__ bias,
                                               float* __restrict__ out) {
    __shared__ float As[2][8][64];    // [buf][n_local][q_local]
    __shared__ float Bs[2][8][256];   // [buf][n_local][col]

    const int qt = blockIdx.x, ot = blockIdx.y, b = blockIdx.z;
    const int q0 = qt * 64, o0 = ot * 4;
    const int t = threadIdx.x;
    const int tcol = t & 31, tq = t >> 5;

    const float* dsb = ds + (size_t)b * NN * NN;

    const int j0 = t >> 6;
    const int ol = (t >> 4) & 3;
    const int l4 = (t & 15) * 4;
    const size_t zb = ((size_t)(b * NC + o0 + ol) * 3) * 32768 + l4;

    unsigned long long acc2[8][4];
#pragma unroll
    for (int i = 0; i < 8; i++)
#pragma unroll
        for (int j = 0; j < 4; j++) acc2[i][j] = pack2(0.f, 0.f);

    float4 pd0, pd1, pm0, pm1, pb0, pb1;

#define K3_LOAD(KK)                                                         \
    {                                                                       \
        int half = ((KK) < 64) ? 1 : 0;                                     \
        int n0 = ((KK) & 63) << 3;                                          \
        if (t < 64) {                                                       \
            const float* dp = dsb + (size_t)(q0 + t) * NN + n0;             \
            pd0 = *(const float4*)dp;                                       \
            pd1 = *(const float4*)(dp + 4);                                 \
            const float* mbase = half ? adj : g_T2;                         \
            const float* mp = mbase + (size_t)(q0 + t) * NN + n0;           \
            pm0 = *(const float4*)mp;                                       \
            pm1 = *(const float4*)(mp + 4);                                 \
        }                                                                   \
        size_t koff = (size_t)(half ? 1 : 2) * 32768;                       \
        pb0 = *(const float4*)&g_z[zb + koff + (size_t)(n0 + j0) * 64];     \
        pb1 = *(const float4*)&g_z[zb + koff + (size_t)(n0 + j0 + 4) * 64]; \
    }

#define K3_STORE(BUF)                                       \
    {                                                       \
        if (t < 64) {                                       \
            As[BUF][0][t] = pd0.x * pm0.x;                  \
            As[BUF][1][t] = pd0.y * pm0.y;                  \
            As[BUF][2][t] = pd0.z * pm0.z;                  \
            As[BUF][3][t] = pd0.w * pm0.w;                  \
            As[BUF][4][t] = pd1.x * pm1.x;                  \
            As[BUF][5][t] = pd1.y * pm1.y;                  \
            As[BUF][6][t] = pd1.z * pm1.z;                  \
            As[BUF][7][t] = pd1.w * pm1.w;                  \
        }                                                   \
        *(float4*)&Bs[BUF][j0][(t & 63) * 4] = pb0;         \
        *(float4*)&Bs[BUF][j0 + 4][(t & 63) * 4] = pb1;     \
    }

    K3_LOAD(0);
    K3_STORE(0);
    __syncthreads();

    for (int kk = 0; kk < 128; kk++) {
        int cur = kk & 1;
        if (kk < 127) K3_LOAD(kk + 1);
#pragma unroll
        for (int j = 0; j < 8; j++) {
            float4 a0 = *(const float4*)&As[cur][j][tq * 4];
            float4 a1 = *(const float4*)&As[cur][j][32 + tq * 4];
            ulonglong2 b0 = *(const ulonglong2*)&Bs[cur][j][tcol * 4];
            ulonglong2 b1 = *(const ulonglong2*)&Bs[cur][j][128 + tcol * 4];
            unsigned long long bp[4] = {b0.x, b0.y, b1.x, b1.y};
            float av[8] = {a0.x, a0.y, a0.z, a0.w, a1.x, a1.y, a1.z, a1.w};
#pragma unroll
            for (int qi = 0; qi < 8; qi++) {
                unsigned long long ap = pack2(av[qi], av[qi]);
#pragma unroll
                for (int cj = 0; cj < 4; cj++)
                    ffma2(acc2[qi][cj], ap, bp[cj]);
            }
        }
        if (kk < 127) K3_STORE(cur ^ 1);
        __syncthreads();
    }

    // Epilogue: + bias[o] + ds[b,q,q] * z0[b,o,q,l]
#pragma unroll
    for (int qi = 0; qi < 8; qi++) {
        int q = q0 + ((qi < 4) ? (tq * 4 + qi) : (32 + tq * 4 + qi - 4));
        float dqq = dsb[(size_t)q * NN + q];
#pragma unroll
        for (int g = 0; g < 2; g++) {
            int col = g * 128 + tcol * 4;
            int o = o0 + (col >> 6);
            int l = col & 63;
            float4 z0 = *(const float4*)&g_z[((size_t)(b * NC + o) * 3) * 32768 +
                                             (size_t)q * 64 + l];
            float bo = bias[o];
            float a0, a1, a2, a3;
            unpack2(acc2[qi][g * 2 + 0], a0, a1);
            unpack2(acc2[qi][g * 2 + 1], a2, a3);
            float4 r;
            r.x = fmaf(dqq, z0.x, a0 + bo);
            r.y = fmaf(dqq, z0.y, a1 + bo);
            r.z = fmaf(dqq, z0.z, a2 + bo);
            r.w = fmaf(dqq, z0.w, a3 + bo);
            *(float4*)&out[(((size_t)b * NC + o) * NN + q) * NL + l] = r;
        }
    }
#undef K3_LOAD
#undef K3_STORE
}

// ---------------------------------------------------------------------------
extern "C" void kernel_launch(void* const* d_in, const int* in_sizes, int n_in,
                              void* d_out, int out_size) {
    const float* x    = (const float*)d_in[0];
    const float* adj  = (const float*)d_in[1];
    const float* ds   = (const float*)d_in[2];
    const float* W    = (const float*)d_in[3];
    const float* bias = (const float*)d_in[4];
    float* out = (float*)d_out;

    k1_T2<<<dim3(32, 32), dim3(16, 16)>>>(adj);
    k2_mix<<<dim3(512, 3, 32), 256>>>(x, W);
    k3_main<<<dim3(8, 16, 32), 256>>>(ds, adj, bias, out);
}

// round 5
// speedup vs baseline: 2.7291x; 2.7291x over previous
#include <cuda_runtime.h>
#include <cuda_bf16.h>
#include <cstdint>
#include <cstddef>

#define NB 32
#define NN 512
#define NL 64
#define NC 64
#define NF 192

__device__ float g_T2[NN * NN];
__device__ float g_z[(size_t)NB * NF * NN * NL];                // [b][f=o*3+k][n][l] fp32
__device__ __nv_bfloat16 g_zth[(size_t)NB * 2 * 64 * 64 * 512]; // [b][k'][o][l][n]
__device__ __nv_bfloat16 g_ztl[(size_t)NB * 2 * 64 * 64 * 512];
__device__ __nv_bfloat16 g_Ah[(size_t)NB * NN * 1024];          // [b][q][n'] n'<512: ds*adj else ds*T2
__device__ __nv_bfloat16 g_Al[(size_t)NB * NN * 1024];

// ---------------- helpers ----------------
__device__ __forceinline__ uint32_t smem_u32(const void* p) {
    uint32_t a;
    asm("{ .reg .u64 t; cvta.to.shared.u64 t, %1; cvt.u32.u64 %0, t; }" : "=r"(a) : "l"(p));
    return a;
}
__device__ __forceinline__ void cp16(uint32_t dst, const void* src) {
    asm volatile("cp.async.cg.shared.global [%0], [%1], 16;" :: "r"(dst), "l"(src));
}
__device__ __forceinline__ void split_bf(float v, unsigned short& h, unsigned short& l) {
    __nv_bfloat16 hb = __float2bfloat16(v);
    float hf = __bfloat162float(hb);
    __nv_bfloat16 lb = __float2bfloat16(v - hf);
    h = *reinterpret_cast<unsigned short*>(&hb);
    l = *reinterpret_cast<unsigned short*>(&lb);
}
__device__ __forceinline__ void ldm4(uint32_t addr, uint32_t* r) {
    asm volatile("ldmatrix.sync.aligned.m8n8.x4.shared.b16 {%0,%1,%2,%3}, [%4];"
                 : "=r"(r[0]), "=r"(r[1]), "=r"(r[2]), "=r"(r[3]) : "r"(addr));
}
__device__ __forceinline__ void mma16816(float* d, const uint32_t* a, const uint32_t* b) {
    asm volatile(
        "mma.sync.aligned.m16n8k16.row.col.f32.bf16.bf16.f32 "
        "{%0,%1,%2,%3}, {%4,%5,%6,%7}, {%8,%9}, {%0,%1,%2,%3};"
        : "+f"(d[0]), "+f"(d[1]), "+f"(d[2]), "+f"(d[3])
        : "r"(a[0]), "r"(a[1]), "r"(a[2]), "r"(a[3]), "r"(b[0]), "r"(b[1]));
}

// ---------------------------------------------------------------------------
// K1: T2 = 2*adj@adj - I
// ---------------------------------------------------------------------------
__global__ void k1_T2(const float* __restrict__ adj) {
    __shared__ float As[16][16];
    __shared__ float Bs[16][17];
    const int tx = threadIdx.x, ty = threadIdx.y;
    const int q = blockIdx.y * 16 + ty;
    const int n = blockIdx.x * 16 + tx;
    float acc = 0.f;
    for (int t0 = 0; t0 < NN; t0 += 16) {
        As[ty][tx] = adj[(size_t)q * NN + t0 + tx];
        Bs[ty][tx] = adj[(size_t)(t0 + ty) * NN + n];
        __syncthreads();
#pragma unroll
        for (int j = 0; j < 16; j++) acc = fmaf(As[ty][j], Bs[j][tx], acc);
        __syncthreads();
    }
    g_T2[(size_t)q * NN + n] = 2.f * acc - (q == n ? 1.f : 0.f);
}

// ---------------------------------------------------------------------------
// kA: A[b][q][n'] = ds[b][q][n]*(n'<512 ? adj : T2)[q][n], bf16 hi/lo split
// ---------------------------------------------------------------------------
__global__ __launch_bounds__(256) void kA(const float* __restrict__ ds,
                                          const float* __restrict__ adj) {
    const int q = blockIdx.x, b = blockIdx.y, t = threadIdx.x;
    const int n4 = t * 4, n = n4 & 511;
    const float* mrow = (n4 < 512 ? adj : g_T2) + (size_t)q * NN + n;
    float4 m = *(const float4*)mrow;
    float4 d = *(const float4*)(ds + ((size_t)b * NN + q) * NN + n);
    float v[4] = {d.x * m.x, d.y * m.y, d.z * m.z, d.w * m.w};
    unsigned short h[4], l[4];
#pragma unroll
    for (int j = 0; j < 4; j++) split_bf(v[j], h[j], l[j]);
    size_t off = ((size_t)b * NN + q) * 1024 + n4;
    *(uint2*)&g_Ah[off] = make_uint2((uint32_t)h[0] | ((uint32_t)h[1] << 16),
                                     (uint32_t)h[2] | ((uint32_t)h[3] << 16));
    *(uint2*)&g_Al[off] = make_uint2((uint32_t)l[0] | ((uint32_t)l[1] << 16),
                                     (uint32_t)l[2] | ((uint32_t)l[3] << 16));
}

// ---------------------------------------------------------------------------
// K2: z[b][f][m] = sum_c Wr[f][c]*x[b][c][m]   (R1-proven scalar version)
// ---------------------------------------------------------------------------
__global__ __launch_bounds__(256) void k2_mix(const float* __restrict__ x,
                                              const float* __restrict__ W) {
    __shared__ float Ws[64][64];
    __shared__ float Xs[64][64];
    const int b = blockIdx.z, f0 = blockIdx.y * 64, m0 = blockIdx.x * 64;
    const int t = threadIdx.x;
#pragma unroll
    for (int i = 0; i < 16; i++) {
        int e = t + i * 256, c = e >> 6, fl = e & 63, f = f0 + fl;
        Ws[c][fl] = W[(f / 3) * NF + c * 3 + (f % 3)];
    }
#pragma unroll
    for (int i = 0; i < 4; i++) {
        int e = t + i * 256, c = e >> 4, mv = e & 15;
        const float* src = x + ((size_t)(b * NC + c)) * 32768 + m0;
        *(float4*)&Xs[c][mv * 4] = ((const float4*)src)[mv];
    }
    __syncthreads();
    const int tm = t & 15, tf = t >> 4;
    float acc[4][4];
#pragma unroll
    for (int i = 0; i < 4; i++)
#pragma unroll
        for (int j = 0; j < 4; j++) acc[i][j] = 0.f;
#pragma unroll
    for (int c = 0; c < 64; c++) {
        float4 a = *(const float4*)&Ws[c][tf * 4];
        float4 bv = *(const float4*)&Xs[c][tm * 4];
        float av[4] = {a.x, a.y, a.z, a.w}, bb[4] = {bv.x, bv.y, bv.z, bv.w};
#pragma unroll
        for (int i = 0; i < 4; i++)
#pragma unroll
            for (int j = 0; j < 4; j++) acc[i][j] = fmaf(av[i], bb[j], acc[i][j]);
    }
#pragma unroll
    for (int i = 0; i < 4; i++) {
        int f = f0 + tf * 4 + i;
        float4 v = make_float4(acc[i][0], acc[i][1], acc[i][2], acc[i][3]);
        *(float4*)&g_z[((size_t)b * NF + f) * 32768 + m0 + tm * 4] = v;
    }
}

// ---------------------------------------------------------------------------
// KT: transpose+split z(k=1,2): [b][f][n][l] fp32 -> [b][k'][o][l][n] bf16 x2
// ---------------------------------------------------------------------------
__global__ __launch_bounds__(256) void kT() {
    __shared__ float Ts[64][65];
    const int n0 = blockIdx.x * 64, o = blockIdx.y;
    const int b = blockIdx.z >> 1, kp = blockIdx.z & 1;
    const int t = threadIdx.x;
    const float* src = g_z + ((size_t)(b * NF + o * 3 + kp + 1)) * 32768 + (size_t)n0 * 64;
#pragma unroll
    for (int i = 0; i < 4; i++) {
        int e = t + i * 256, nr = e >> 4, lv = (e & 15) * 4;
        float4 v = *(const float4*)(src + (size_t)nr * 64 + lv);
        Ts[nr][lv] = v.x; Ts[nr][lv + 1] = v.y; Ts[nr][lv + 2] = v.z; Ts[nr][lv + 3] = v.w;
    }
    __syncthreads();
    size_t obase = (((size_t)(b * 2 + kp) * 64 + o) * 64) * 512 + n0;
#pragma unroll
    for (int i = 0; i < 2; i++) {
        int e = t + i * 256, lr = e >> 3, nv = (e & 7) * 8;
        unsigned short h[8], l[8];
#pragma unroll
        for (int j = 0; j < 8; j++) split_bf(Ts[nv + j][lr], h[j], l[j]);
        size_t off = obase + (size_t)lr * 512 + nv;
        *(uint4*)&g_zth[off] = make_uint4(
            (uint32_t)h[0] | ((uint32_t)h[1] << 16), (uint32_t)h[2] | ((uint32_t)h[3] << 16),
            (uint32_t)h[4] | ((uint32_t)h[5] << 16), (uint32_t)h[6] | ((uint32_t)h[7] << 16));
        *(uint4*)&g_ztl[off] = make_uint4(
            (uint32_t)l[0] | ((uint32_t)l[1] << 16), (uint32_t)l[2] | ((uint32_t)l[3] << 16),
            (uint32_t)l[4] | ((uint32_t)l[5] << 16), (uint32_t)l[6] | ((uint32_t)l[7] << 16));
    }
}

// ---------------------------------------------------------------------------
// K3: mma.sync bf16-split GEMM. CTA 128(q) x 128(col), K=1024, 32-n chunks.
// smem rows padded to 80B (ldmatrix bank-conflict-free).
// ---------------------------------------------------------------------------
#define ROWB 80
#define MATB (128 * ROWB)     // 10240
#define STAGEB (4 * MATB)     // 40960: Ah | Al | Bh | Bl
#define SMEM_K3 (2 * STAGEB)  // 81920

__device__ __forceinline__ void k3_load(uint32_t sb, int b, int q0, int colT,
                                        int stg, int kk) {
    const int t = threadIdx.x;
    const uint32_t st = sb + stg * STAGEB;
    const int half = kk >> 4;
    const char* Ah = (const char*)g_Ah + (((size_t)(b * NN + q0)) * 1024 + (size_t)kk * 32) * 2;
    const char* Al = (const char*)g_Al + (((size_t)(b * NN + q0)) * 1024 + (size_t)kk * 32) * 2;
    size_t bo = (((size_t)(b * 2 + half) * 4096 + colT) * 512 + (size_t)(kk & 15) * 32) * 2;
    const char* Bh = (const char*)g_zth + bo;
    const char* Bl = (const char*)g_ztl + bo;
    const int u16 = (t & 3) * 16;
#pragma unroll
    for (int i = 0; i < 8; i++) {
        const int mat = i >> 1;                         // 0:Ah 1:Al 2:Bh 3:Bl
        const int idx2 = t + (i & 1) * 256;             // 0..511
        const int r = idx2 >> 2;                        // row 0..127
        const uint32_t dst = st + mat * MATB + r * ROWB + u16;
        const char* src;
        size_t stride;
        if (mat == 0)      { src = Ah; stride = 2048; }
        else if (mat == 1) { src = Al; stride = 2048; }
        else if (mat == 2) { src = Bh; stride = 1024; }
        else               { src = Bl; stride = 1024; }
        cp16(dst, src + (size_t)r * stride + u16);
    }
}

__global__ __launch_bounds__(256, 2) void k3_main(const float* __restrict__ ds,
                                                  const float* __restrict__ bias,
                                                  float* __restrict__ out) {
    extern __shared__ __align__(128) char smem[];
    const uint32_t sb = smem_u32(smem);
    const int t = threadIdx.x, lane = t & 31, wid = t >> 5;
    const int q0 = blockIdx.x * 128, colT = blockIdx.y * 128, b = blockIdx.z;
    const int warpM = wid >> 2, warpN = wid & 3;

    // ldmatrix per-lane geometry
    const int lr = lane & 7, seg = lane >> 3;
    const int aRow = warpM * 64 + lr + (seg & 1) * 8;     // + mf*16
    const int aCol = (seg >> 1) * 16;                     // + s*32
    const int bRow = warpN * 32 + lr + (seg >> 1) * 8;    // + nfp*16
    const int bCol = (seg & 1) * 16;                      // + s*32

    float d[4][4][4];
#pragma unroll
    for (int m = 0; m < 4; m++)
#pragma unroll
        for (int n = 0; n < 4; n++)
#pragma unroll
            for (int e = 0; e < 4; e++) d[m][n][e] = 0.f;

    k3_load(sb, b, q0, colT, 0, 0);
    asm volatile("cp.async.commit_group;");
    k3_load(sb, b, q0, colT, 1, 1);
    asm volatile("cp.async.commit_group;");

    for (int kk = 0; kk < 32; kk++) {
        const int cur = kk & 1;
        if (kk < 30) asm volatile("cp.async.wait_group 1;" ::: "memory");
        else         asm volatile("cp.async.wait_group 0;" ::: "memory");
        __syncthreads();
        const uint32_t st = sb + cur * STAGEB;
#pragma unroll
        for (int s = 0; s < 2; s++) {
            uint32_t bh[4][2], bl[4][2], a[4][4];
#pragma unroll
            for (int nfp = 0; nfp < 2; nfp++) {
                uint32_t r4[4];
                ldm4(st + 2 * MATB + (bRow + nfp * 16) * ROWB + bCol + s * 32, r4);
                bh[nfp * 2][0] = r4[0]; bh[nfp * 2][1] = r4[1];
                bh[nfp * 2 + 1][0] = r4[2]; bh[nfp * 2 + 1][1] = r4[3];
                ldm4(st + 3 * MATB + (bRow + nfp * 16) * ROWB + bCol + s * 32, r4);
                bl[nfp * 2][0] = r4[0]; bl[nfp * 2][1] = r4[1];
                bl[nfp * 2 + 1][0] = r4[2]; bl[nfp * 2 + 1][1] = r4[3];
            }
#pragma unroll
            for (int mf = 0; mf < 4; mf++)
                ldm4(st + (aRow + mf * 16) * ROWB + aCol + s * 32, a[mf]);
#pragma unroll
            for (int mf = 0; mf < 4; mf++)
#pragma unroll
                for (int nf = 0; nf < 4; nf++) {
                    mma16816(d[mf][nf], a[mf], bh[nf]);
                    mma16816(d[mf][nf], a[mf], bl[nf]);
                }
#pragma unroll
            for (int mf = 0; mf < 4; mf++)
                ldm4(st + MATB + (aRow + mf * 16) * ROWB + aCol + s * 32, a[mf]);
#pragma unroll
            for (int mf = 0; mf < 4; mf++)
#pragma unroll
                for (int nf = 0; nf < 4; nf++)
                    mma16816(d[mf][nf], a[mf], bh[nf]);
        }
        __syncthreads();
        if (kk < 30) {
            k3_load(sb, b, q0, colT, cur, kk + 2);
            asm volatile("cp.async.commit_group;");
        }
    }

    // Epilogue: C -> out with bias + ds[q,q]*z0
    const int group = lane >> 2, tig = lane & 3;
#pragma unroll
    for (int mf = 0; mf < 4; mf++) {
#pragma unroll
        for (int half = 0; half < 2; half++) {
            const int q = q0 + warpM * 64 + mf * 16 + group + half * 8;
            const float dqq = ds[((size_t)b * NN + q) * NN + q];
#pragma unroll
            for (int nf = 0; nf < 4; nf++) {
                const int colg = colT + warpN * 32 + nf * 8 + tig * 2;
                const int o = colg >> 6, l = colg & 63;
                const float bo = bias[o];
                const float* z0p = g_z + ((size_t)(b * NF + o * 3)) * 32768 +
                                   (size_t)q * 64 + l;
                float2 z0 = *(const float2*)z0p;
                float2 r;
                r.x = fmaf(dqq, z0.x, d[mf][nf][half * 2 + 0] + bo);
                r.y = fmaf(dqq, z0.y, d[mf][nf][half * 2 + 1] + bo);
                *(float2*)&out[(((size_t)(b * NC + o)) * NN + q) * 64 + l] = r;
            }
        }
    }
}

// ---------------------------------------------------------------------------
extern "C" void kernel_launch(void* const* d_in, const int* in_sizes, int n_in,
                              void* d_out, int out_size) {
    const float* x    = (const float*)d_in[0];
    const float* adj  = (const float*)d_in[1];
    const float* ds   = (const float*)d_in[2];
    const float* W    = (const float*)d_in[3];
    const float* bias = (const float*)d_in[4];
    float* out = (float*)d_out;

    cudaFuncSetAttribute(k3_main, cudaFuncAttributeMaxDynamicSharedMemorySize, SMEM_K3);

    k1_T2<<<dim3(32, 32), dim3(16, 16)>>>(adj);
    kA<<<dim3(512, 32), 256>>>(ds, adj);
    k2_mix<<<dim3(512, 3, 32), 256>>>(x, W);
    kT<<<dim3(8, 64, 64), 256>>>();
    k3_main<<<dim3(4, 32, 32), 256, SMEM_K3>>>(ds, bias, out);
}

// round 7
// speedup vs baseline: 3.8605x; 1.4145x over previous
#include <cuda_runtime.h>
#include <cuda_bf16.h>
#include <cstdint>
#include <cstddef>

#define NB 32
#define NN 512
#define NL 64
#define NC 64
#define NF 192

// ---------------- scratch ----------------
__device__ float g_T2[NN * NN];
__device__ float g_z0[(size_t)NB * 64 * NN * NL];               // [b][o][n][l] fp32 (k=0 term)
__device__ __nv_bfloat16 g_zbh[(size_t)NB * 2 * 64 * NN * NL];  // [b][kp][o][n][l] hi
__device__ __nv_bfloat16 g_zbl[(size_t)NB * 2 * 64 * NN * NL];  // lo
__device__ __nv_bfloat16 g_Ah[(size_t)NB * NN * 1024];          // [b][q][n'] hi
__device__ __nv_bfloat16 g_Al[(size_t)NB * NN * 1024];          // lo
__device__ __nv_bfloat16 g_Wh[NF * 64];                         // [f=k*64+o][c] hi
__device__ __nv_bfloat16 g_Wl[NF * 64];                         // lo

// ---------------- helpers ----------------
__device__ __forceinline__ uint32_t smem_u32(const void* p) {
    uint32_t a;
    asm("{ .reg .u64 t; cvta.to.shared.u64 t, %1; cvt.u32.u64 %0, t; }" : "=r"(a) : "l"(p));
    return a;
}
__device__ __forceinline__ void cp16(uint32_t dst, const void* src) {
    asm volatile("cp.async.cg.shared.global [%0], [%1], 16;" :: "r"(dst), "l"(src));
}
__device__ __forceinline__ void split_bf(float v, unsigned short& h, unsigned short& l) {
    __nv_bfloat16 hb = __float2bfloat16(v);
    float hf = __bfloat162float(hb);
    __nv_bfloat16 lb = __float2bfloat16(v - hf);
    h = *reinterpret_cast<unsigned short*>(&hb);
    l = *reinterpret_cast<unsigned short*>(&lb);
}
__device__ __forceinline__ void ldm4(uint32_t addr, uint32_t* r) {
    asm volatile("ldmatrix.sync.aligned.m8n8.x4.shared.b16 {%0,%1,%2,%3}, [%4];"
                 : "=r"(r[0]), "=r"(r[1]), "=r"(r[2]), "=r"(r[3]) : "r"(addr));
}
__device__ __forceinline__ void ldm4t(uint32_t addr, uint32_t* r) {
    asm volatile("ldmatrix.sync.aligned.m8n8.x4.trans.shared.b16 {%0,%1,%2,%3}, [%4];"
                 : "=r"(r[0]), "=r"(r[1]), "=r"(r[2]), "=r"(r[3]) : "r"(addr));
}
__device__ __forceinline__ void mma16816(float* d, const uint32_t* a, const uint32_t* b) {
    asm volatile(
        "mma.sync.aligned.m16n8k16.row.col.f32.bf16.bf16.f32 "
        "{%0,%1,%2,%3}, {%4,%5,%6,%7}, {%8,%9}, {%0,%1,%2,%3};"
        : "+f"(d[0]), "+f"(d[1]), "+f"(d[2]), "+f"(d[3])
        : "r"(a[0]), "r"(a[1]), "r"(a[2]), "r"(a[3]), "r"(b[0]), "r"(b[1]));
}

// ---------------------------------------------------------------------------
// K1: T2 = 2*adj@adj - I
// ---------------------------------------------------------------------------
__global__ void k1_T2(const float* __restrict__ adj) {
    __shared__ float As[16][16];
    __shared__ float Bs[16][17];
    const int tx = threadIdx.x, ty = threadIdx.y;
    const int q = blockIdx.y * 16 + ty;
    const int n = blockIdx.x * 16 + tx;
    float acc = 0.f;
    for (int t0 = 0; t0 < NN; t0 += 16) {
        As[ty][tx] = adj[(size_t)q * NN + t0 + tx];
        Bs[ty][tx] = adj[(size_t)(t0 + ty) * NN + n];
        __syncthreads();
#pragma unroll
        for (int j = 0; j < 16; j++) acc = fmaf(As[ty][j], Bs[j][tx], acc);
        __syncthreads();
    }
    g_T2[(size_t)q * NN + n] = 2.f * acc - (q == n ? 1.f : 0.f);
}

// ---------------------------------------------------------------------------
// kA: A[b][q][n'] = ds[b][q][n]*(n'<512 ? adj : T2)[q][n], bf16 hi/lo split
// ---------------------------------------------------------------------------
__global__ __launch_bounds__(256) void kA(const float* __restrict__ ds,
                                          const float* __restrict__ adj) {
    const int q = blockIdx.x, b = blockIdx.y, t = threadIdx.x;
    const int n4 = t * 4, n = n4 & 511;
    const float* mrow = (n4 < 512 ? adj : g_T2) + (size_t)q * NN + n;
    float4 m = *(const float4*)mrow;
    float4 d = *(const float4*)(ds + ((size_t)b * NN + q) * NN + n);
    float v[4] = {d.x * m.x, d.y * m.y, d.z * m.z, d.w * m.w};
    unsigned short h[4], l[4];
#pragma unroll
    for (int j = 0; j < 4; j++) split_bf(v[j], h[j], l[j]);
    size_t off = ((size_t)b * NN + q) * 1024 + n4;
    *(uint2*)&g_Ah[off] = make_uint2((uint32_t)h[0] | ((uint32_t)h[1] << 16),
                                     (uint32_t)h[2] | ((uint32_t)h[3] << 16));
    *(uint2*)&g_Al[off] = make_uint2((uint32_t)l[0] | ((uint32_t)l[1] << 16),
                                     (uint32_t)l[2] | ((uint32_t)l[3] << 16));
}

// ---------------------------------------------------------------------------
// kW: split W into g_Wh/g_Wl, row f = k*64+o, col c.  Wr[f][c]=W[o*192+c*3+k]
// ---------------------------------------------------------------------------
__global__ void kW(const float* __restrict__ W) {
    int idx = blockIdx.x * 256 + threadIdx.x;           // 0..3071
    if (idx >= NF * 16) return;
    int f = idx >> 4, c4 = (idx & 15) * 4;
    int k = f >> 6, o = f & 63;
    unsigned short h[4], l[4];
#pragma unroll
    for (int j = 0; j < 4; j++) split_bf(W[o * NF + (c4 + j) * 3 + k], h[j], l[j]);
    *(uint2*)&g_Wh[f * 64 + c4] = make_uint2((uint32_t)h[0] | ((uint32_t)h[1] << 16),
                                             (uint32_t)h[2] | ((uint32_t)h[3] << 16));
    *(uint2*)&g_Wl[f * 64 + c4] = make_uint2((uint32_t)l[0] | ((uint32_t)l[1] << 16),
                                             (uint32_t)l[2] | ((uint32_t)l[3] << 16));
}

// ---------------------------------------------------------------------------
// K2 (mma): z[f][m] = sum_c Wr[f][c]*x[b][c][m], f-tile 192, m-tile 64, K=64.
// 3-term bf16 split.  Outputs: f<64 -> g_z0 fp32; else split bf16 -> g_zbh/l.
// ---------------------------------------------------------------------------
#define K2_WH 0
#define K2_WL 27648
#define K2_XH 55296
#define K2_XL 64512
#define K2_SMEM 73728

__global__ __launch_bounds__(256, 2) void k2_mma(const float* __restrict__ x) {
    extern __shared__ __align__(128) char smem[];
    const uint32_t sb = smem_u32(smem);
    const int t = threadIdx.x, lane = t & 31, wid = t >> 5;
    const int m0 = blockIdx.x * 64, b = blockIdx.y;

    // W tiles: 192 rows x 128B data (pad to 144)
#pragma unroll
    for (int i = 0; i < 6; i++) {
        int idx = t + i * 256, r = idx >> 3, sg = idx & 7;
        cp16(sb + K2_WH + r * 144 + sg * 16, (const char*)g_Wh + r * 128 + sg * 16);
        cp16(sb + K2_WL + r * 144 + sg * 16, (const char*)g_Wl + r * 128 + sg * 16);
    }
    asm volatile("cp.async.commit_group;");

    // x tile: 64c x 64m fp32 -> split into Xh/Xl [c][m] bf16 (rows 128B, pad 144)
#pragma unroll
    for (int i = 0; i < 4; i++) {
        int idx = t + i * 256, c = idx >> 4, sg = idx & 15;
        float4 v = *(const float4*)(x + ((size_t)(b * NC + c)) * 32768 + m0 + sg * 4);
        unsigned short h[4], l[4];
        split_bf(v.x, h[0], l[0]); split_bf(v.y, h[1], l[1]);
        split_bf(v.z, h[2], l[2]); split_bf(v.w, h[3], l[3]);
        *(uint2*)(smem + K2_XH + c * 144 + sg * 8) =
            make_uint2((uint32_t)h[0] | ((uint32_t)h[1] << 16),
                       (uint32_t)h[2] | ((uint32_t)h[3] << 16));
        *(uint2*)(smem + K2_XL + c * 144 + sg * 8) =
            make_uint2((uint32_t)l[0] | ((uint32_t)l[1] << 16),
                       (uint32_t)l[2] | ((uint32_t)l[3] << 16));
    }
    asm volatile("cp.async.wait_group 0;" ::: "memory");
    __syncthreads();

    const int warpM = wid >> 1, warpN = wid & 1;
    const int lr = lane & 7, seg = lane >> 3;
    float d[3][4][4];
#pragma unroll
    for (int i = 0; i < 3; i++)
#pragma unroll
        for (int j = 0; j < 4; j++)
#pragma unroll
            for (int e = 0; e < 4; e++) d[i][j][e] = 0.f;

#pragma unroll
    for (int s = 0; s < 4; s++) {
        uint32_t ah[3][4], al_[3][4], bh[4][2], bl[4][2];
#pragma unroll
        for (int mf = 0; mf < 3; mf++) {
            uint32_t row = warpM * 48 + mf * 16 + lr + (seg & 1) * 8;
            uint32_t col = (seg >> 1) * 16 + s * 32;
            ldm4(sb + K2_WH + row * 144 + col, ah[mf]);
            ldm4(sb + K2_WL + row * 144 + col, al_[mf]);
        }
#pragma unroll
        for (int g = 0; g < 2; g++) {
            uint32_t row = s * 16 + lr + (seg & 1) * 8;
            uint32_t col = warpN * 64 + g * 32 + (seg >> 1) * 16;
            uint32_t r4[4];
            ldm4t(sb + K2_XH + row * 144 + col, r4);
            bh[g * 2][0] = r4[0]; bh[g * 2][1] = r4[1];
            bh[g * 2 + 1][0] = r4[2]; bh[g * 2 + 1][1] = r4[3];
            ldm4t(sb + K2_XL + row * 144 + col, r4);
            bl[g * 2][0] = r4[0]; bl[g * 2][1] = r4[1];
            bl[g * 2 + 1][0] = r4[2]; bl[g * 2 + 1][1] = r4[3];
        }
#pragma unroll
        for (int mf = 0; mf < 3; mf++)
#pragma unroll
            for (int nf = 0; nf < 4; nf++) {
                mma16816(d[mf][nf], ah[mf], bh[nf]);
                mma16816(d[mf][nf], ah[mf], bl[nf]);
                mma16816(d[mf][nf], al_[mf], bh[nf]);
            }
    }

    // epilogue
    const int group = lane >> 2, tig = lane & 3;
#pragma unroll
    for (int mf = 0; mf < 3; mf++)
#pragma unroll
        for (int half = 0; half < 2; half++) {
            int f = warpM * 48 + mf * 16 + group + half * 8;
            int k = f >> 6, o = f & 63;
#pragma unroll
            for (int nf = 0; nf < 4; nf++) {
                int m = m0 + warpN * 32 + nf * 8 + tig * 2;
                float c0 = d[mf][nf][half * 2], c1 = d[mf][nf][half * 2 + 1];
                if (k == 0) {
                    *(float2*)&g_z0[(size_t)(b * 64 + o) * 32768 + m] =
                        make_float2(c0, c1);
                } else {
                    unsigned short h0, l0, h1, l1;
                    split_bf(c0, h0, l0); split_bf(c1, h1, l1);
                    size_t off = (size_t)((b * 2 + k - 1) * 64 + o) * 32768 + m;
                    *(uint32_t*)&g_zbh[off] = (uint32_t)h0 | ((uint32_t)h1 << 16);
                    *(uint32_t*)&g_zbl[off] = (uint32_t)l0 | ((uint32_t)l1 << 16);
                }
            }
        }
}

// ---------------------------------------------------------------------------
// K3: mma.sync bf16-split GEMM.  CTA 128(q) x 128(col = 2o x 64l), K=1024 in
// 32-n chunks.  B loaded row-major [n][col] with ldmatrix.trans.
// ---------------------------------------------------------------------------
#define OFF_AH 0
#define OFF_AL 10240
#define OFF_BH 20480
#define OFF_BL 29184
#define STAGEB 37888
#define SMEM_K3 (2 * STAGEB)

__device__ __forceinline__ void k3_load(uint32_t sb, int b, int q0, int o0,
                                        int stg, int kk) {
    const int t = threadIdx.x;
    const uint32_t st = sb + stg * STAGEB;
    const int kp = kk >> 4, n0 = (kk & 15) * 32;
    // A: 128 q-rows x 64B (32 k x bf16), row pad 80  -- 512 segs per matrix
#pragma unroll
    for (int i = 0; i < 2; i++) {
        int idx = t + i * 256;                  // 0..511
        int r = idx >> 2, u = (idx & 3) * 16;   // r: 0..127
        const char* pa = (const char*)g_Ah + ((size_t)(b * NN + q0 + r)) * 2048 + kk * 64 + u;
        const char* pb = (const char*)g_Al + ((size_t)(b * NN + q0 + r)) * 2048 + kk * 64 + u;
        cp16(st + OFF_AH + r * 80 + u, pa);
        cp16(st + OFF_AL + r * 80 + u, pb);
    }
    // B: 32 n-rows x 256B (2o x 64l x bf16), row pad 272
#pragma unroll
    for (int i = 0; i < 2; i++) {
        int idx = t + i * 256, nl = idx >> 4, sg = idx & 15;
        int ol = sg >> 3, l16 = (sg & 7) * 16;
        size_t src = ((size_t)((b * 2 + kp) * 64 + o0 + ol) * 512 + n0 + nl) * 128 + l16;
        cp16(st + OFF_BH + nl * 272 + sg * 16, (const char*)g_zbh + src);
        cp16(st + OFF_BL + nl * 272 + sg * 16, (const char*)g_zbl + src);
    }
}

__global__ __launch_bounds__(256, 2) void k3_main(const float* __restrict__ ds,
                                                  const float* __restrict__ bias,
                                                  float* __restrict__ out) {
    extern __shared__ __align__(128) char smem[];
    const uint32_t sb = smem_u32(smem);
    const int t = threadIdx.x, lane = t & 31, wid = t >> 5;
    const int q0 = blockIdx.x * 128, colT = blockIdx.y * 128, b = blockIdx.z;
    const int o0 = blockIdx.y * 2;
    const int warpM = wid >> 2, warpN = wid & 3;
    const int lr = lane & 7, seg = lane >> 3;

    float d[4][4][4];
#pragma unroll
    for (int m = 0; m < 4; m++)
#pragma unroll
        for (int n = 0; n < 4; n++)
#pragma unroll
            for (int e = 0; e < 4; e++) d[m][n][e] = 0.f;

    k3_load(sb, b, q0, o0, 0, 0);
    asm volatile("cp.async.commit_group;");
    k3_load(sb, b, q0, o0, 1, 1);
    asm volatile("cp.async.commit_group;");

    for (int kk = 0; kk < 32; kk++) {
        const int cur = kk & 1;
        if (kk < 30) asm volatile("cp.async.wait_group 1;" ::: "memory");
        else         asm volatile("cp.async.wait_group 0;" ::: "memory");
        __syncthreads();
        const uint32_t st = sb + cur * STAGEB;
#pragma unroll
        for (int s = 0; s < 2; s++) {
            uint32_t bh[4][2], bl[4][2], a[4][4];
#pragma unroll
            for (int g = 0; g < 2; g++) {
                uint32_t row = s * 16 + lr + (seg & 1) * 8;
                uint32_t col = warpN * 64 + g * 32 + (seg >> 1) * 16;
                uint32_t r4[4];
                ldm4t(st + OFF_BH + row * 272 + col, r4);
                bh[g * 2][0] = r4[0]; bh[g * 2][1] = r4[1];
                bh[g * 2 + 1][0] = r4[2]; bh[g * 2 + 1][1] = r4[3];
                ldm4t(st + OFF_BL + row * 272 + col, r4);
                bl[g * 2][0] = r4[0]; bl[g * 2][1] = r4[1];
                bl[g * 2 + 1][0] = r4[2]; bl[g * 2 + 1][1] = r4[3];
            }
#pragma unroll
            for (int mf = 0; mf < 4; mf++) {
                uint32_t row = warpM * 64 + mf * 16 + lr + (seg & 1) * 8;
                ldm4(st + OFF_AH + row * 80 + (seg >> 1) * 16 + s * 32, a[mf]);
            }
#pragma unroll
            for (int mf = 0; mf < 4; mf++)
#pragma unroll
                for (int nf = 0; nf < 4; nf++) {
                    mma16816(d[mf][nf], a[mf], bh[nf]);
                    mma16816(d[mf][nf], a[mf], bl[nf]);
                }
#pragma unroll
            for (int mf = 0; mf < 4; mf++) {
                uint32_t row = warpM * 64 + mf * 16 + lr + (seg & 1) * 8;
                ldm4(st + OFF_AL + row * 80 + (seg >> 1) * 16 + s * 32, a[mf]);
            }
#pragma unroll
            for (int mf = 0; mf < 4; mf++)
#pragma unroll
                for (int nf = 0; nf < 4; nf++)
                    mma16816(d[mf][nf], a[mf], bh[nf]);
        }
        __syncthreads();
        if (kk < 30) {
            k3_load(sb, b, q0, o0, cur, kk + 2);
            asm volatile("cp.async.commit_group;");
        }
    }

    // Epilogue: + bias + ds[q,q]*z0
    const int group = lane >> 2, tig = lane & 3;
#pragma unroll
    for (int mf = 0; mf < 4; mf++)
#pragma unroll
        for (int half = 0; half < 2; half++) {
            const int q = q0 + warpM * 64 + mf * 16 + group + half * 8;
            const float dqq = ds[((size_t)b * NN + q) * NN + q];
#pragma unroll
            for (int nf = 0; nf < 4; nf++) {
                const int colg = colT + warpN * 32 + nf * 8 + tig * 2;
                const int o = colg >> 6, l = colg & 63;
                const float bo = bias[o];
                float2 z0 = *(const float2*)&g_z0[(size_t)(b * 64 + o) * 32768 +
                                                  (size_t)q * 64 + l];
                float2 r;
                r.x = fmaf(dqq, z0.x, d[mf][nf][half * 2 + 0] + bo);
                r.y = fmaf(dqq, z0.y, d[mf][nf][half * 2 + 1] + bo);
                *(float2*)&out[(((size_t)(b * NC + o)) * NN + q) * 64 + l] = r;
            }
        }
}

// ---------------------------------------------------------------------------
extern "C" void kernel_launch(void* const* d_in, const int* in_sizes, int n_in,
                              void* d_out, int out_size) {
    const float* x    = (const float*)d_in[0];
    const float* adj  = (const float*)d_in[1];
    const float* ds   = (const float*)d_in[2];
    const float* W    = (const float*)d_in[3];
    const float* bias = (const float*)d_in[4];
    float* out = (float*)d_out;

    cudaFuncSetAttribute(k2_mma, cudaFuncAttributeMaxDynamicSharedMemorySize, K2_SMEM);
    cudaFuncSetAttribute(k3_main, cudaFuncAttributeMaxDynamicSharedMemorySize, SMEM_K3);

    k1_T2<<<dim3(32, 32), dim3(16, 16)>>>(adj);
    kA<<<dim3(512, 32), 256>>>(ds, adj);
    kW<<<12, 256>>>(W);
    k2_mma<<<dim3(512, 32), 256, K2_SMEM>>>(x);
    k3_main<<<dim3(4, 32, 32), 256, SMEM_K3>>>(ds, bias, out);
}

// round 8
// speedup vs baseline: 3.9865x; 1.0327x over previous
#include <cuda_runtime.h>
#include <cuda_bf16.h>
#include <cstdint>
#include <cstddef>

#define NB 32
#define NN 512
#define NL 64
#define NC 64
#define NF 192

// ---------------- scratch ----------------
__device__ float g_T2[NN * NN];
__device__ float g_z0[(size_t)NB * 64 * NN * NL];               // [b][o][n][l] fp32 (k=0 term)
__device__ __nv_bfloat16 g_zbh[(size_t)NB * 2 * 64 * NN * NL];  // [b][kp][o][n][l] hi
__device__ __nv_bfloat16 g_zbl[(size_t)NB * 2 * 64 * NN * NL];  // lo
__device__ __nv_bfloat16 g_Ah[(size_t)NB * NN * 1024];          // [b][q][n'] hi
__device__ __nv_bfloat16 g_Al[(size_t)NB * NN * 1024];          // lo
__device__ __nv_bfloat16 g_Wh[NF * 64];                         // [f=k*64+o][c] hi
__device__ __nv_bfloat16 g_Wl[NF * 64];                         // lo

// ---------------- helpers ----------------
__device__ __forceinline__ uint32_t smem_u32(const void* p) {
    uint32_t a;
    asm("{ .reg .u64 t; cvta.to.shared.u64 t, %1; cvt.u32.u64 %0, t; }" : "=r"(a) : "l"(p));
    return a;
}
__device__ __forceinline__ void cp16(uint32_t dst, const void* src) {
    asm volatile("cp.async.cg.shared.global [%0], [%1], 16;" :: "r"(dst), "l"(src));
}
__device__ __forceinline__ void split_bf(float v, unsigned short& h, unsigned short& l) {
    __nv_bfloat16 hb = __float2bfloat16(v);
    float hf = __bfloat162float(hb);
    __nv_bfloat16 lb = __float2bfloat16(v - hf);
    h = *reinterpret_cast<unsigned short*>(&hb);
    l = *reinterpret_cast<unsigned short*>(&lb);
}
__device__ __forceinline__ void ldm4(uint32_t addr, uint32_t* r) {
    asm volatile("ldmatrix.sync.aligned.m8n8.x4.shared.b16 {%0,%1,%2,%3}, [%4];"
                 : "=r"(r[0]), "=r"(r[1]), "=r"(r[2]), "=r"(r[3]) : "r"(addr));
}
__device__ __forceinline__ void ldm4t(uint32_t addr, uint32_t* r) {
    asm volatile("ldmatrix.sync.aligned.m8n8.x4.trans.shared.b16 {%0,%1,%2,%3}, [%4];"
                 : "=r"(r[0]), "=r"(r[1]), "=r"(r[2]), "=r"(r[3]) : "r"(addr));
}
__device__ __forceinline__ void mma16816(float* d, const uint32_t* a, const uint32_t* b) {
    asm volatile(
        "mma.sync.aligned.m16n8k16.row.col.f32.bf16.bf16.f32 "
        "{%0,%1,%2,%3}, {%4,%5,%6,%7}, {%8,%9}, {%0,%1,%2,%3};"
        : "+f"(d[0]), "+f"(d[1]), "+f"(d[2]), "+f"(d[3])
        : "r"(a[0]), "r"(a[1]), "r"(a[2]), "r"(a[3]), "r"(b[0]), "r"(b[1]));
}

// ---------------------------------------------------------------------------
// K1: T2 = 2*adj@adj - I
// ---------------------------------------------------------------------------
__global__ void k1_T2(const float* __restrict__ adj) {
    __shared__ float As[16][16];
    __shared__ float Bs[16][17];
    const int tx = threadIdx.x, ty = threadIdx.y;
    const int q = blockIdx.y * 16 + ty;
    const int n = blockIdx.x * 16 + tx;
    float acc = 0.f;
    for (int t0 = 0; t0 < NN; t0 += 16) {
        As[ty][tx] = adj[(size_t)q * NN + t0 + tx];
        Bs[ty][tx] = adj[(size_t)(t0 + ty) * NN + n];
        __syncthreads();
#pragma unroll
        for (int j = 0; j < 16; j++) acc = fmaf(As[ty][j], Bs[j][tx], acc);
        __syncthreads();
    }
    g_T2[(size_t)q * NN + n] = 2.f * acc - (q == n ? 1.f : 0.f);
}

// ---------------------------------------------------------------------------
// kA: A[b][q][n'] = ds[b][q][n]*(n'<512 ? adj : T2)[q][n], bf16 hi/lo split
// ---------------------------------------------------------------------------
__global__ __launch_bounds__(256) void kA(const float* __restrict__ ds,
                                          const float* __restrict__ adj) {
    const int q = blockIdx.x, b = blockIdx.y, t = threadIdx.x;
    const int n4 = t * 4, n = n4 & 511;
    const float* mrow = (n4 < 512 ? adj : g_T2) + (size_t)q * NN + n;
    float4 m = *(const float4*)mrow;
    float4 d = *(const float4*)(ds + ((size_t)b * NN + q) * NN + n);
    float v[4] = {d.x * m.x, d.y * m.y, d.z * m.z, d.w * m.w};
    unsigned short h[4], l[4];
#pragma unroll
    for (int j = 0; j < 4; j++) split_bf(v[j], h[j], l[j]);
    size_t off = ((size_t)b * NN + q) * 1024 + n4;
    *(uint2*)&g_Ah[off] = make_uint2((uint32_t)h[0] | ((uint32_t)h[1] << 16),
                                     (uint32_t)h[2] | ((uint32_t)h[3] << 16));
    *(uint2*)&g_Al[off] = make_uint2((uint32_t)l[0] | ((uint32_t)l[1] << 16),
                                     (uint32_t)l[2] | ((uint32_t)l[3] << 16));
}

// ---------------------------------------------------------------------------
// kW: split W into g_Wh/g_Wl, row f = k*64+o, col c.  Wr[f][c]=W[o*192+c*3+k]
// ---------------------------------------------------------------------------
__global__ void kW(const float* __restrict__ W) {
    int idx = blockIdx.x * 256 + threadIdx.x;           // 0..3071
    if (idx >= NF * 16) return;
    int f = idx >> 4, c4 = (idx & 15) * 4;
    int k = f >> 6, o = f & 63;
    unsigned short h[4], l[4];
#pragma unroll
    for (int j = 0; j < 4; j++) split_bf(W[o * NF + (c4 + j) * 3 + k], h[j], l[j]);
    *(uint2*)&g_Wh[f * 64 + c4] = make_uint2((uint32_t)h[0] | ((uint32_t)h[1] << 16),
                                             (uint32_t)h[2] | ((uint32_t)h[3] << 16));
    *(uint2*)&g_Wl[f * 64 + c4] = make_uint2((uint32_t)l[0] | ((uint32_t)l[1] << 16),
                                             (uint32_t)l[2] | ((uint32_t)l[3] << 16));
}

// ---------------------------------------------------------------------------
// K2 (mma, v2): per CTA a 256-m strip: W resident, 4 x-subtiles pipelined.
// z[f][m] = sum_c Wr[f][c]*x[b][c][m]; f<64 -> g_z0 fp32; else split bf16.
// ---------------------------------------------------------------------------
#define K2_WH 0
#define K2_WL 27648
#define K2_XBASE 55296
#define K2_XSTRIDE 18432          // per buffer: XH(9216) + XL(9216)
#define K2_SMEM 92160

__global__ __launch_bounds__(256, 2) void k2_mma(const float* __restrict__ x) {
    extern __shared__ __align__(128) char smem[];
    const uint32_t sb = smem_u32(smem);
    const int t = threadIdx.x, lane = t & 31, wid = t >> 5;
    const int mT = blockIdx.x * 256, b = blockIdx.y;

    // W tiles: 192 rows x 128B data (pad to 144), resident for all 4 subtiles
#pragma unroll
    for (int i = 0; i < 6; i++) {
        int idx = t + i * 256, r = idx >> 3, sg8 = idx & 7;
        cp16(sb + K2_WH + r * 144 + sg8 * 16, (const char*)g_Wh + r * 128 + sg8 * 16);
        cp16(sb + K2_WL + r * 144 + sg8 * 16, (const char*)g_Wl + r * 128 + sg8 * 16);
    }
    asm volatile("cp.async.commit_group;");
    asm volatile("cp.async.wait_group 0;" ::: "memory");

    const int warpM = wid >> 1, warpN = wid & 1;
    const int lr = lane & 7, seg = lane >> 3;
    const int group = lane >> 2, tig = lane & 3;

    // x-load geometry: sg fixed, c = cbase + 16*i
    const int sg = t & 15, cbase = t >> 4;
    const float* xb_ptr = x + (size_t)b * NC * 32768 + sg * 4;

    float4 xr[4];
#pragma unroll
    for (int i = 0; i < 4; i++)
        xr[i] = *(const float4*)(xb_ptr + ((size_t)(cbase + 16 * i)) * 32768 + mT);

    for (int sub = 0; sub < 4; sub++) {
        const uint32_t xbuf = sb + K2_XBASE + (sub & 1) * K2_XSTRIDE;
        // convert + store current subtile
#pragma unroll
        for (int i = 0; i < 4; i++) {
            int c = cbase + 16 * i;
            unsigned short h[4], l[4];
            split_bf(xr[i].x, h[0], l[0]); split_bf(xr[i].y, h[1], l[1]);
            split_bf(xr[i].z, h[2], l[2]); split_bf(xr[i].w, h[3], l[3]);
            *(uint2*)(smem + (xbuf - sb) + c * 144 + sg * 8) =
                make_uint2((uint32_t)h[0] | ((uint32_t)h[1] << 16),
                           (uint32_t)h[2] | ((uint32_t)h[3] << 16));
            *(uint2*)(smem + (xbuf - sb) + 9216 + c * 144 + sg * 8) =
                make_uint2((uint32_t)l[0] | ((uint32_t)l[1] << 16),
                           (uint32_t)l[2] | ((uint32_t)l[3] << 16));
        }
        __syncthreads();
        // prefetch next subtile into registers (overlaps with compute)
        if (sub < 3) {
#pragma unroll
            for (int i = 0; i < 4; i++)
                xr[i] = *(const float4*)(xb_ptr + ((size_t)(cbase + 16 * i)) * 32768 +
                                         mT + (sub + 1) * 64);
        }

        float d[3][4][4];
#pragma unroll
        for (int i = 0; i < 3; i++)
#pragma unroll
            for (int j = 0; j < 4; j++)
#pragma unroll
                for (int e = 0; e < 4; e++) d[i][j][e] = 0.f;

#pragma unroll
        for (int s = 0; s < 4; s++) {
            uint32_t ah[3][4], al_[3][4], bh[4][2], bl[4][2];
#pragma unroll
            for (int mf = 0; mf < 3; mf++) {
                uint32_t row = warpM * 48 + mf * 16 + lr + (seg & 1) * 8;
                uint32_t col = (seg >> 1) * 16 + s * 32;
                ldm4(sb + K2_WH + row * 144 + col, ah[mf]);
                ldm4(sb + K2_WL + row * 144 + col, al_[mf]);
            }
#pragma unroll
            for (int g = 0; g < 2; g++) {
                uint32_t row = s * 16 + lr + (seg & 1) * 8;
                uint32_t col = warpN * 64 + g * 32 + (seg >> 1) * 16;
                uint32_t r4[4];
                ldm4t(xbuf + row * 144 + col, r4);
                bh[g * 2][0] = r4[0]; bh[g * 2][1] = r4[1];
                bh[g * 2 + 1][0] = r4[2]; bh[g * 2 + 1][1] = r4[3];
                ldm4t(xbuf + 9216 + row * 144 + col, r4);
                bl[g * 2][0] = r4[0]; bl[g * 2][1] = r4[1];
                bl[g * 2 + 1][0] = r4[2]; bl[g * 2 + 1][1] = r4[3];
            }
#pragma unroll
            for (int mf = 0; mf < 3; mf++)
#pragma unroll
                for (int nf = 0; nf < 4; nf++) {
                    mma16816(d[mf][nf], ah[mf], bh[nf]);
                    mma16816(d[mf][nf], ah[mf], bl[nf]);
                    mma16816(d[mf][nf], al_[mf], bh[nf]);
                }
        }

        // epilogue for this subtile
        const int m0 = mT + sub * 64;
#pragma unroll
        for (int mf = 0; mf < 3; mf++)
#pragma unroll
            for (int half = 0; half < 2; half++) {
                int f = warpM * 48 + mf * 16 + group + half * 8;
                int k = f >> 6, o = f & 63;
#pragma unroll
                for (int nf = 0; nf < 4; nf++) {
                    int m = m0 + warpN * 32 + nf * 8 + tig * 2;
                    float c0 = d[mf][nf][half * 2], c1 = d[mf][nf][half * 2 + 1];
                    if (k == 0) {
                        *(float2*)&g_z0[(size_t)(b * 64 + o) * 32768 + m] =
                            make_float2(c0, c1);
                    } else {
                        unsigned short h0, l0, h1, l1;
                        split_bf(c0, h0, l0); split_bf(c1, h1, l1);
                        size_t off = (size_t)((b * 2 + k - 1) * 64 + o) * 32768 + m;
                        *(uint32_t*)&g_zbh[off] = (uint32_t)h0 | ((uint32_t)h1 << 16);
                        *(uint32_t*)&g_zbl[off] = (uint32_t)l0 | ((uint32_t)l1 << 16);
                    }
                }
            }
    }
}

// ---------------------------------------------------------------------------
// K3: mma.sync bf16-split GEMM.  CTA 128(q) x 128(col = 2o x 64l), K=1024 in
// 32-n chunks.  B loaded row-major [n][col] with ldmatrix.trans.
// ---------------------------------------------------------------------------
#define OFF_AH 0
#define OFF_AL 10240
#define OFF_BH 20480
#define OFF_BL 29184
#define STAGEB 37888
#define SMEM_K3 (2 * STAGEB)

__device__ __forceinline__ void k3_load(uint32_t sb, int b, int q0, int o0,
                                        int stg, int kk) {
    const int t = threadIdx.x;
    const uint32_t st = sb + stg * STAGEB;
    const int kp = kk >> 4, n0 = (kk & 15) * 32;
    // A: 128 q-rows x 64B (32 k x bf16), row pad 80  -- 512 segs per matrix
#pragma unroll
    for (int i = 0; i < 2; i++) {
        int idx = t + i * 256;                  // 0..511
        int r = idx >> 2, u = (idx & 3) * 16;   // r: 0..127
        const char* pa = (const char*)g_Ah + ((size_t)(b * NN + q0 + r)) * 2048 + kk * 64 + u;
        const char* pb = (const char*)g_Al + ((size_t)(b * NN + q0 + r)) * 2048 + kk * 64 + u;
        cp16(st + OFF_AH + r * 80 + u, pa);
        cp16(st + OFF_AL + r * 80 + u, pb);
    }
    // B: 32 n-rows x 256B (2o x 64l x bf16), row pad 272
#pragma unroll
    for (int i = 0; i < 2; i++) {
        int idx = t + i * 256, nl = idx >> 4, sg = idx & 15;
        int ol = sg >> 3, l16 = (sg & 7) * 16;
        size_t src = ((size_t)((b * 2 + kp) * 64 + o0 + ol) * 512 + n0 + nl) * 128 + l16;
        cp16(st + OFF_BH + nl * 272 + sg * 16, (const char*)g_zbh + src);
        cp16(st + OFF_BL + nl * 272 + sg * 16, (const char*)g_zbl + src);
    }
}

__global__ __launch_bounds__(256, 2) void k3_main(const float* __restrict__ ds,
                                                  const float* __restrict__ bias,
                                                  float* __restrict__ out) {
    extern __shared__ __align__(128) char smem[];
    const uint32_t sb = smem_u32(smem);
    const int t = threadIdx.x, lane = t & 31, wid = t >> 5;
    const int q0 = blockIdx.x * 128, colT = blockIdx.y * 128, b = blockIdx.z;
    const int o0 = blockIdx.y * 2;
    const int warpM = wid >> 2, warpN = wid & 3;
    const int lr = lane & 7, seg = lane >> 3;

    float d[4][4][4];
#pragma unroll
    for (int m = 0; m < 4; m++)
#pragma unroll
        for (int n = 0; n < 4; n++)
#pragma unroll
            for (int e = 0; e < 4; e++) d[m][n][e] = 0.f;

    k3_load(sb, b, q0, o0, 0, 0);
    asm volatile("cp.async.commit_group;");
    k3_load(sb, b, q0, o0, 1, 1);
    asm volatile("cp.async.commit_group;");

    for (int kk = 0; kk < 32; kk++) {
        const int cur = kk & 1;
        if (kk < 30) asm volatile("cp.async.wait_group 1;" ::: "memory");
        else         asm volatile("cp.async.wait_group 0;" ::: "memory");
        __syncthreads();
        const uint32_t st = sb + cur * STAGEB;
#pragma unroll
        for (int s = 0; s < 2; s++) {
            uint32_t bh[4][2], bl[4][2], a[4][4];
#pragma unroll
            for (int g = 0; g < 2; g++) {
                uint32_t row = s * 16 + lr + (seg & 1) * 8;
                uint32_t col = warpN * 64 + g * 32 + (seg >> 1) * 16;
                uint32_t r4[4];
                ldm4t(st + OFF_BH + row * 272 + col, r4);
                bh[g * 2][0] = r4[0]; bh[g * 2][1] = r4[1];
                bh[g * 2 + 1][0] = r4[2]; bh[g * 2 + 1][1] = r4[3];
                ldm4t(st + OFF_BL + row * 272 + col, r4);
                bl[g * 2][0] = r4[0]; bl[g * 2][1] = r4[1];
                bl[g * 2 + 1][0] = r4[2]; bl[g * 2 + 1][1] = r4[3];
            }
#pragma unroll
            for (int mf = 0; mf < 4; mf++) {
                uint32_t row = warpM * 64 + mf * 16 + lr + (seg & 1) * 8;
                ldm4(st + OFF_AH + row * 80 + (seg >> 1) * 16 + s * 32, a[mf]);
            }
#pragma unroll
            for (int mf = 0; mf < 4; mf++)
#pragma unroll
                for (int nf = 0; nf < 4; nf++) {
                    mma16816(d[mf][nf], a[mf], bh[nf]);
                    mma16816(d[mf][nf], a[mf], bl[nf]);
                }
#pragma unroll
            for (int mf = 0; mf < 4; mf++) {
                uint32_t row = warpM * 64 + mf * 16 + lr + (seg & 1) * 8;
                ldm4(st + OFF_AL + row * 80 + (seg >> 1) * 16 + s * 32, a[mf]);
            }
#pragma unroll
            for (int mf = 0; mf < 4; mf++)
#pragma unroll
                for (int nf = 0; nf < 4; nf++)
                    mma16816(d[mf][nf], a[mf], bh[nf]);
        }
        __syncthreads();
        if (kk < 30) {
            k3_load(sb, b, q0, o0, cur, kk + 2);
            asm volatile("cp.async.commit_group;");
        }
    }

    // Epilogue: + bias + ds[q,q]*z0
    const int group = lane >> 2, tig = lane & 3;
#pragma unroll
    for (int mf = 0; mf < 4; mf++)
#pragma unroll
        for (int half = 0; half < 2; half++) {
            const int q = q0 + warpM * 64 + mf * 16 + group + half * 8;
            const float dqq = ds[((size_t)b * NN + q) * NN + q];
#pragma unroll
            for (int nf = 0; nf < 4; nf++) {
                const int colg = colT + warpN * 32 + nf * 8 + tig * 2;
                const int o = colg >> 6, l = colg & 63;
                const float bo = bias[o];
                float2 z0 = *(const float2*)&g_z0[(size_t)(b * 64 + o) * 32768 +
                                                  (size_t)q * 64 + l];
                float2 r;
                r.x = fmaf(dqq, z0.x, d[mf][nf][half * 2 + 0] + bo);
                r.y = fmaf(dqq, z0.y, d[mf][nf][half * 2 + 1] + bo);
                *(float2*)&out[(((size_t)(b * NC + o)) * NN + q) * 64 + l] = r;
            }
        }
}

// ---------------------------------------------------------------------------
extern "C" void kernel_launch(void* const* d_in, const int* in_sizes, int n_in,
                              void* d_out, int out_size) {
    const float* x    = (const float*)d_in[0];
    const float* adj  = (const float*)d_in[1];
    const float* ds   = (const float*)d_in[2];
    const float* W    = (const float*)d_in[3];
    const float* bias = (const float*)d_in[4];
    float* out = (float*)d_out;

    cudaFuncSetAttribute(k2_mma, cudaFuncAttributeMaxDynamicSharedMemorySize, K2_SMEM);
    cudaFuncSetAttribute(k3_main, cudaFuncAttributeMaxDynamicSharedMemorySize, SMEM_K3);

    k1_T2<<<dim3(32, 32), dim3(16, 16)>>>(adj);
    kA<<<dim3(512, 32), 256>>>(ds, adj);
    kW<<<12, 256>>>(W);
    k2_mma<<<dim3(128, 32), 256, K2_SMEM>>>(x);
    k3_main<<<dim3(4, 32, 32), 256, SMEM_K3>>>(ds, bias, out);
}

// round 9
// speedup vs baseline: 5.4405x; 1.3647x over previous
#include <cuda_runtime.h>
#include <cuda_fp16.h>
#include <cstdint>
#include <cstddef>

#define NB 32
#define NN 512
#define NL 64
#define NC 64
#define NF 192

// ---------------- scratch ----------------
__device__ float g_T2[NN * NN];
__device__ float g_z0[(size_t)NB * 64 * NN * NL];          // [b][o][n][l] fp32 (k=0 term)
__device__ __half g_zbh[(size_t)NB * 2 * 64 * NN * NL];    // [b][kp][o][n][l] hi
__device__ __half g_zbl[(size_t)NB * 2 * 64 * NN * NL];    // lo
__device__ __half g_Af[(size_t)NB * NN * 1024];            // [b][q][n'] single fp16
__device__ __half g_Wf[NF * 64];                           // [f=k*64+o][c] single fp16

// ---------------- helpers ----------------
__device__ __forceinline__ uint32_t smem_u32(const void* p) {
    uint32_t a;
    asm("{ .reg .u64 t; cvta.to.shared.u64 t, %1; cvt.u32.u64 %0, t; }" : "=r"(a) : "l"(p));
    return a;
}
__device__ __forceinline__ void cp16(uint32_t dst, const void* src) {
    asm volatile("cp.async.cg.shared.global [%0], [%1], 16;" :: "r"(dst), "l"(src));
}
__device__ __forceinline__ void split_h(float v, unsigned short& h, unsigned short& l) {
    __half hb = __float2half_rn(v);
    float hf = __half2float(hb);
    __half lb = __float2half_rn(v - hf);
    h = *reinterpret_cast<unsigned short*>(&hb);
    l = *reinterpret_cast<unsigned short*>(&lb);
}
__device__ __forceinline__ unsigned short to_h(float v) {
    __half hb = __float2half_rn(v);
    return *reinterpret_cast<unsigned short*>(&hb);
}
__device__ __forceinline__ void ldm4(uint32_t addr, uint32_t* r) {
    asm volatile("ldmatrix.sync.aligned.m8n8.x4.shared.b16 {%0,%1,%2,%3}, [%4];"
                 : "=r"(r[0]), "=r"(r[1]), "=r"(r[2]), "=r"(r[3]) : "r"(addr));
}
__device__ __forceinline__ void ldm4t(uint32_t addr, uint32_t* r) {
    asm volatile("ldmatrix.sync.aligned.m8n8.x4.trans.shared.b16 {%0,%1,%2,%3}, [%4];"
                 : "=r"(r[0]), "=r"(r[1]), "=r"(r[2]), "=r"(r[3]) : "r"(addr));
}
__device__ __forceinline__ void mma16816(float* d, const uint32_t* a, const uint32_t* b) {
    asm volatile(
        "mma.sync.aligned.m16n8k16.row.col.f32.f16.f16.f32 "
        "{%0,%1,%2,%3}, {%4,%5,%6,%7}, {%8,%9}, {%0,%1,%2,%3};"
        : "+f"(d[0]), "+f"(d[1]), "+f"(d[2]), "+f"(d[3])
        : "r"(a[0]), "r"(a[1]), "r"(a[2]), "r"(a[3]), "r"(b[0]), "r"(b[1]));
}

// ---------------------------------------------------------------------------
// K1: T2 = 2*adj@adj - I
// ---------------------------------------------------------------------------
__global__ void k1_T2(const float* __restrict__ adj) {
    __shared__ float As[16][16];
    __shared__ float Bs[16][17];
    const int tx = threadIdx.x, ty = threadIdx.y;
    const int q = blockIdx.y * 16 + ty;
    const int n = blockIdx.x * 16 + tx;
    float acc = 0.f;
    for (int t0 = 0; t0 < NN; t0 += 16) {
        As[ty][tx] = adj[(size_t)q * NN + t0 + tx];
        Bs[ty][tx] = adj[(size_t)(t0 + ty) * NN + n];
        __syncthreads();
#pragma unroll
        for (int j = 0; j < 16; j++) acc = fmaf(As[ty][j], Bs[j][tx], acc);
        __syncthreads();
    }
    g_T2[(size_t)q * NN + n] = 2.f * acc - (q == n ? 1.f : 0.f);
}

// ---------------------------------------------------------------------------
// kA: A[b][q][n'] = ds[b][q][n]*(n'<512 ? adj : T2)[q][n] -> single fp16
// ---------------------------------------------------------------------------
__global__ __launch_bounds__(256) void kA(const float* __restrict__ ds,
                                          const float* __restrict__ adj) {
    const int q = blockIdx.x, b = blockIdx.y, t = threadIdx.x;
    const int n4 = t * 4, n = n4 & 511;
    const float* mrow = (n4 < 512 ? adj : g_T2) + (size_t)q * NN + n;
    float4 m = *(const float4*)mrow;
    float4 d = *(const float4*)(ds + ((size_t)b * NN + q) * NN + n);
    unsigned short h[4] = {to_h(d.x * m.x), to_h(d.y * m.y),
                           to_h(d.z * m.z), to_h(d.w * m.w)};
    size_t off = ((size_t)b * NN + q) * 1024 + n4;
    *(uint2*)&g_Af[off] = make_uint2((uint32_t)h[0] | ((uint32_t)h[1] << 16),
                                     (uint32_t)h[2] | ((uint32_t)h[3] << 16));
}

// ---------------------------------------------------------------------------
// kW: W -> single fp16, row f = k*64+o, col c.  Wr[f][c]=W[o*192+c*3+k]
// ---------------------------------------------------------------------------
__global__ void kW(const float* __restrict__ W) {
    int idx = blockIdx.x * 256 + threadIdx.x;
    if (idx >= NF * 16) return;
    int f = idx >> 4, c4 = (idx & 15) * 4;
    int k = f >> 6, o = f & 63;
    unsigned short h[4];
#pragma unroll
    for (int j = 0; j < 4; j++) h[j] = to_h(W[o * NF + (c4 + j) * 3 + k]);
    *(uint2*)&g_Wf[f * 64 + c4] = make_uint2((uint32_t)h[0] | ((uint32_t)h[1] << 16),
                                             (uint32_t)h[2] | ((uint32_t)h[3] << 16));
}

// ---------------------------------------------------------------------------
// K2 (mma): per CTA a 256-m strip; W resident (single fp16), x split hi/lo.
// z[f][m] = sum_c Wr[f][c]*x[b][c][m]; 2 MMA terms: W*Xh + W*Xl.
// ---------------------------------------------------------------------------
#define K2_W 0
#define K2_XBASE 27648
#define K2_XSTRIDE 18432          // per buffer: XH(9216) + XL(9216)
#define K2_SMEM 64512

__global__ __launch_bounds__(256, 2) void k2_mma(const float* __restrict__ x) {
    extern __shared__ __align__(128) char smem[];
    const uint32_t sb = smem_u32(smem);
    const int t = threadIdx.x, lane = t & 31, wid = t >> 5;
    const int mT = blockIdx.x * 256, b = blockIdx.y;

    // W tile: 192 rows x 128B (pad 144)
#pragma unroll
    for (int i = 0; i < 6; i++) {
        int idx = t + i * 256, r = idx >> 3, sg8 = idx & 7;
        cp16(sb + K2_W + r * 144 + sg8 * 16, (const char*)g_Wf + r * 128 + sg8 * 16);
    }
    asm volatile("cp.async.commit_group;");
    asm volatile("cp.async.wait_group 0;" ::: "memory");

    const int warpM = wid >> 1, warpN = wid & 1;
    const int lr = lane & 7, seg = lane >> 3;
    const int group = lane >> 2, tig = lane & 3;

    const int sg = t & 15, cbase = t >> 4;
    const float* xb_ptr = x + (size_t)b * NC * 32768 + sg * 4;

    float4 xr[4];
#pragma unroll
    for (int i = 0; i < 4; i++)
        xr[i] = *(const float4*)(xb_ptr + ((size_t)(cbase + 16 * i)) * 32768 + mT);

    for (int sub = 0; sub < 4; sub++) {
        const uint32_t xbuf = sb + K2_XBASE + (sub & 1) * K2_XSTRIDE;
#pragma unroll
        for (int i = 0; i < 4; i++) {
            int c = cbase + 16 * i;
            unsigned short h[4], l[4];
            split_h(xr[i].x, h[0], l[0]); split_h(xr[i].y, h[1], l[1]);
            split_h(xr[i].z, h[2], l[2]); split_h(xr[i].w, h[3], l[3]);
            *(uint2*)(smem + (xbuf - sb) + c * 144 + sg * 8) =
                make_uint2((uint32_t)h[0] | ((uint32_t)h[1] << 16),
                           (uint32_t)h[2] | ((uint32_t)h[3] << 16));
            *(uint2*)(smem + (xbuf - sb) + 9216 + c * 144 + sg * 8) =
                make_uint2((uint32_t)l[0] | ((uint32_t)l[1] << 16),
                           (uint32_t)l[2] | ((uint32_t)l[3] << 16));
        }
        __syncthreads();
        if (sub < 3) {
#pragma unroll
            for (int i = 0; i < 4; i++)
                xr[i] = *(const float4*)(xb_ptr + ((size_t)(cbase + 16 * i)) * 32768 +
                                         mT + (sub + 1) * 64);
        }

        float d[3][4][4];
#pragma unroll
        for (int i = 0; i < 3; i++)
#pragma unroll
            for (int j = 0; j < 4; j++)
#pragma unroll
                for (int e = 0; e < 4; e++) d[i][j][e] = 0.f;

#pragma unroll
        for (int s = 0; s < 4; s++) {
            uint32_t a[3][4], bh[4][2], bl[4][2];
#pragma unroll
            for (int mf = 0; mf < 3; mf++) {
                uint32_t row = warpM * 48 + mf * 16 + lr + (seg & 1) * 8;
                uint32_t col = (seg >> 1) * 16 + s * 32;
                ldm4(sb + K2_W + row * 144 + col, a[mf]);
            }
#pragma unroll
            for (int g = 0; g < 2; g++) {
                uint32_t row = s * 16 + lr + (seg & 1) * 8;
                uint32_t col = warpN * 64 + g * 32 + (seg >> 1) * 16;
                uint32_t r4[4];
                ldm4t(xbuf + row * 144 + col, r4);
                bh[g * 2][0] = r4[0]; bh[g * 2][1] = r4[1];
                bh[g * 2 + 1][0] = r4[2]; bh[g * 2 + 1][1] = r4[3];
                ldm4t(xbuf + 9216 + row * 144 + col, r4);
                bl[g * 2][0] = r4[0]; bl[g * 2][1] = r4[1];
                bl[g * 2 + 1][0] = r4[2]; bl[g * 2 + 1][1] = r4[3];
            }
#pragma unroll
            for (int mf = 0; mf < 3; mf++)
#pragma unroll
                for (int nf = 0; nf < 4; nf++) {
                    mma16816(d[mf][nf], a[mf], bh[nf]);
                    mma16816(d[mf][nf], a[mf], bl[nf]);
                }
        }

        const int m0 = mT + sub * 64;
#pragma unroll
        for (int mf = 0; mf < 3; mf++)
#pragma unroll
            for (int half = 0; half < 2; half++) {
                int f = warpM * 48 + mf * 16 + group + half * 8;
                int k = f >> 6, o = f & 63;
#pragma unroll
                for (int nf = 0; nf < 4; nf++) {
                    int m = m0 + warpN * 32 + nf * 8 + tig * 2;
                    float c0 = d[mf][nf][half * 2], c1 = d[mf][nf][half * 2 + 1];
                    if (k == 0) {
                        *(float2*)&g_z0[(size_t)(b * 64 + o) * 32768 + m] =
                            make_float2(c0, c1);
                    } else {
                        unsigned short h0, l0, h1, l1;
                        split_h(c0, h0, l0); split_h(c1, h1, l1);
                        size_t off = (size_t)((b * 2 + k - 1) * 64 + o) * 32768 + m;
                        *(uint32_t*)&g_zbh[off] = (uint32_t)h0 | ((uint32_t)h1 << 16);
                        *(uint32_t*)&g_zbl[off] = (uint32_t)l0 | ((uint32_t)l1 << 16);
                    }
                }
            }
    }
}

// ---------------------------------------------------------------------------
// K3: fp16 mma GEMM, 2 terms (A*Bh + A*Bl).  CTA 128(q) x 128(col), K=1024
// in 32-n chunks, 3-stage cp.async ring.
// ---------------------------------------------------------------------------
#define OFF_A 0
#define OFF_BH 10240
#define OFF_BL 18944
#define STAGEB 27648
#define SMEM_K3 (3 * STAGEB)

__device__ __forceinline__ void k3_load(uint32_t sb, int b, int q0, int o0,
                                        int stg, int kk) {
    const int t = threadIdx.x;
    const uint32_t st = sb + stg * STAGEB;
    const int kp = kk >> 4, n0 = (kk & 15) * 32;
    // A: 128 q-rows x 64B (32 k halves), pad 80
#pragma unroll
    for (int i = 0; i < 2; i++) {
        int idx = t + i * 256;
        int r = idx >> 2, u = (idx & 3) * 16;
        cp16(st + OFF_A + r * 80 + u,
             (const char*)g_Af + ((size_t)(b * NN + q0 + r)) * 2048 + kk * 64 + u);
    }
    // B: 32 n-rows x 256B (2o x 64l halves), pad 272
#pragma unroll
    for (int i = 0; i < 2; i++) {
        int idx = t + i * 256, nl = idx >> 4, sg = idx & 15;
        int ol = sg >> 3, l16 = (sg & 7) * 16;
        size_t src = ((size_t)((b * 2 + kp) * 64 + o0 + ol) * 512 + n0 + nl) * 128 + l16;
        cp16(st + OFF_BH + nl * 272 + sg * 16, (const char*)g_zbh + src);
        cp16(st + OFF_BL + nl * 272 + sg * 16, (const char*)g_zbl + src);
    }
}

__global__ __launch_bounds__(256, 2) void k3_main(const float* __restrict__ ds,
                                                  const float* __restrict__ bias,
                                                  float* __restrict__ out) {
    extern __shared__ __align__(128) char smem[];
    const uint32_t sb = smem_u32(smem);
    const int t = threadIdx.x, lane = t & 31, wid = t >> 5;
    const int q0 = blockIdx.x * 128, colT = blockIdx.y * 128, b = blockIdx.z;
    const int o0 = blockIdx.y * 2;
    const int warpM = wid >> 2, warpN = wid & 3;
    const int lr = lane & 7, seg = lane >> 3;

    float d[4][4][4];
#pragma unroll
    for (int m = 0; m < 4; m++)
#pragma unroll
        for (int n = 0; n < 4; n++)
#pragma unroll
            for (int e = 0; e < 4; e++) d[m][n][e] = 0.f;

    k3_load(sb, b, q0, o0, 0, 0);
    asm volatile("cp.async.commit_group;");
    k3_load(sb, b, q0, o0, 1, 1);
    asm volatile("cp.async.commit_group;");
    k3_load(sb, b, q0, o0, 2, 2);
    asm volatile("cp.async.commit_group;");

    int cur = 0;
    for (int kk = 0; kk < 32; kk++) {
        if (kk < 30)      asm volatile("cp.async.wait_group 2;" ::: "memory");
        else if (kk == 30) asm volatile("cp.async.wait_group 1;" ::: "memory");
        else               asm volatile("cp.async.wait_group 0;" ::: "memory");
        __syncthreads();
        const uint32_t st = sb + cur * STAGEB;
#pragma unroll
        for (int s = 0; s < 2; s++) {
            uint32_t bh[4][2], bl[4][2], a[4][4];
#pragma unroll
            for (int g = 0; g < 2; g++) {
                uint32_t row = s * 16 + lr + (seg & 1) * 8;
                uint32_t col = warpN * 64 + g * 32 + (seg >> 1) * 16;
                uint32_t r4[4];
                ldm4t(st + OFF_BH + row * 272 + col, r4);
                bh[g * 2][0] = r4[0]; bh[g * 2][1] = r4[1];
                bh[g * 2 + 1][0] = r4[2]; bh[g * 2 + 1][1] = r4[3];
                ldm4t(st + OFF_BL + row * 272 + col, r4);
                bl[g * 2][0] = r4[0]; bl[g * 2][1] = r4[1];
                bl[g * 2 + 1][0] = r4[2]; bl[g * 2 + 1][1] = r4[3];
            }
#pragma unroll
            for (int mf = 0; mf < 4; mf++) {
                uint32_t row = warpM * 64 + mf * 16 + lr + (seg & 1) * 8;
                ldm4(st + OFF_A + row * 80 + (seg >> 1) * 16 + s * 32, a[mf]);
            }
#pragma unroll
            for (int mf = 0; mf < 4; mf++)
#pragma unroll
                for (int nf = 0; nf < 4; nf++) {
                    mma16816(d[mf][nf], a[mf], bh[nf]);
                    mma16816(d[mf][nf], a[mf], bl[nf]);
                }
        }
        __syncthreads();
        if (kk < 29) {
            k3_load(sb, b, q0, o0, cur, kk + 3);
            asm volatile("cp.async.commit_group;");
        }
        cur = (cur == 2) ? 0 : cur + 1;
    }

    // Epilogue: + bias + ds[q,q]*z0
    const int group = lane >> 2, tig = lane & 3;
#pragma unroll
    for (int mf = 0; mf < 4; mf++)
#pragma unroll
        for (int half = 0; half < 2; half++) {
            const int q = q0 + warpM * 64 + mf * 16 + group + half * 8;
            const float dqq = ds[((size_t)b * NN + q) * NN + q];
#pragma unroll
            for (int nf = 0; nf < 4; nf++) {
                const int colg = colT + warpN * 32 + nf * 8 + tig * 2;
                const int o = colg >> 6, l = colg & 63;
                const float bo = bias[o];
                float2 z0 = *(const float2*)&g_z0[(size_t)(b * 64 + o) * 32768 +
                                                  (size_t)q * 64 + l];
                float2 r;
                r.x = fmaf(dqq, z0.x, d[mf][nf][half * 2 + 0] + bo);
                r.y = fmaf(dqq, z0.y, d[mf][nf][half * 2 + 1] + bo);
                *(float2*)&out[(((size_t)(b * NC + o)) * NN + q) * 64 + l] = r;
            }
        }
}

// ---------------------------------------------------------------------------
extern "C" void kernel_launch(void* const* d_in, const int* in_sizes, int n_in,
                              void* d_out, int out_size) {
    const float* x    = (const float*)d_in[0];
    const float* adj  = (const float*)d_in[1];
    const float* ds   = (const float*)d_in[2];
    const float* W    = (const float*)d_in[3];
    const float* bias = (const float*)d_in[4];
    float* out = (float*)d_out;

    cudaFuncSetAttribute(k2_mma, cudaFuncAttributeMaxDynamicSharedMemorySize, K2_SMEM);
    cudaFuncSetAttribute(k3_main, cudaFuncAttributeMaxDynamicSharedMemorySize, SMEM_K3);

    k1_T2<<<dim3(32, 32), dim3(16, 16)>>>(adj);
    kA<<<dim3(512, 32), 256>>>(ds, adj);
    kW<<<12, 256>>>(W);
    k2_mma<<<dim3(128, 32), 256, K2_SMEM>>>(x);
    k3_main<<<dim3(4, 32, 32), 256, SMEM_K3>>>(ds, bias, out);
}

// round 10
// speedup vs baseline: 7.9355x; 1.4586x over previous
#include <cuda_runtime.h>
#include <cuda_fp16.h>
#include <cstdint>
#include <cstddef>

#define NB 32
#define NN 512
#define NL 64
#define NC 64
#define NF 192

// ---------------- scratch ----------------
__device__ float g_T2[NN * NN];
__device__ float g_z0[(size_t)NB * 64 * NN * NL];          // [b][o][n][l] fp32 (k=0 term)
__device__ __half g_zf[(size_t)NB * 2 * 64 * NN * NL];     // [b][kp][o][n][l] single fp16
__device__ __half g_Af[(size_t)NB * NN * 1024];            // [b][q][n'] single fp16
__device__ __half g_Wf[NF * 64];                           // [f=k*64+o][c] single fp16

// ---------------- helpers ----------------
__device__ __forceinline__ uint32_t smem_u32(const void* p) {
    uint32_t a;
    asm("{ .reg .u64 t; cvta.to.shared.u64 t, %1; cvt.u32.u64 %0, t; }" : "=r"(a) : "l"(p));
    return a;
}
__device__ __forceinline__ void cp16(uint32_t dst, const void* src) {
    asm volatile("cp.async.cg.shared.global [%0], [%1], 16;" :: "r"(dst), "l"(src));
}
__device__ __forceinline__ void split_h(float v, unsigned short& h, unsigned short& l) {
    __half hb = __float2half_rn(v);
    float hf = __half2float(hb);
    __half lb = __float2half_rn(v - hf);
    h = *reinterpret_cast<unsigned short*>(&hb);
    l = *reinterpret_cast<unsigned short*>(&lb);
}
__device__ __forceinline__ unsigned short to_h(float v) {
    __half hb = __float2half_rn(v);
    return *reinterpret_cast<unsigned short*>(&hb);
}
__device__ __forceinline__ void ldm4(uint32_t addr, uint32_t* r) {
    asm volatile("ldmatrix.sync.aligned.m8n8.x4.shared.b16 {%0,%1,%2,%3}, [%4];"
                 : "=r"(r[0]), "=r"(r[1]), "=r"(r[2]), "=r"(r[3]) : "r"(addr));
}
__device__ __forceinline__ void ldm4t(uint32_t addr, uint32_t* r) {
    asm volatile("ldmatrix.sync.aligned.m8n8.x4.trans.shared.b16 {%0,%1,%2,%3}, [%4];"
                 : "=r"(r[0]), "=r"(r[1]), "=r"(r[2]), "=r"(r[3]) : "r"(addr));
}
__device__ __forceinline__ void mma16816(float* d, const uint32_t* a, const uint32_t* b) {
    asm volatile(
        "mma.sync.aligned.m16n8k16.row.col.f32.f16.f16.f32 "
        "{%0,%1,%2,%3}, {%4,%5,%6,%7}, {%8,%9}, {%0,%1,%2,%3};"
        : "+f"(d[0]), "+f"(d[1]), "+f"(d[2]), "+f"(d[3])
        : "r"(a[0]), "r"(a[1]), "r"(a[2]), "r"(a[3]), "r"(b[0]), "r"(b[1]));
}

// ---------------------------------------------------------------------------
// K1: T2 = 2*adj@adj - I
// ---------------------------------------------------------------------------
__global__ void k1_T2(const float* __restrict__ adj) {
    __shared__ float As[16][16];
    __shared__ float Bs[16][17];
    const int tx = threadIdx.x, ty = threadIdx.y;
    const int q = blockIdx.y * 16 + ty;
    const int n = blockIdx.x * 16 + tx;
    float acc = 0.f;
    for (int t0 = 0; t0 < NN; t0 += 16) {
        As[ty][tx] = adj[(size_t)q * NN + t0 + tx];
        Bs[ty][tx] = adj[(size_t)(t0 + ty) * NN + n];
        __syncthreads();
#pragma unroll
        for (int j = 0; j < 16; j++) acc = fmaf(As[ty][j], Bs[j][tx], acc);
        __syncthreads();
    }
    g_T2[(size_t)q * NN + n] = 2.f * acc - (q == n ? 1.f : 0.f);
}

// ---------------------------------------------------------------------------
// kA: A[b][q][n'] = ds[b][q][n]*(n'<512 ? adj : T2)[q][n] -> single fp16
// ---------------------------------------------------------------------------
__global__ __launch_bounds__(256) void kA(const float* __restrict__ ds,
                                          const float* __restrict__ adj) {
    const int q = blockIdx.x, b = blockIdx.y, t = threadIdx.x;
    const int n4 = t * 4, n = n4 & 511;
    const float* mrow = (n4 < 512 ? adj : g_T2) + (size_t)q * NN + n;
    float4 m = *(const float4*)mrow;
    float4 d = *(const float4*)(ds + ((size_t)b * NN + q) * NN + n);
    unsigned short h[4] = {to_h(d.x * m.x), to_h(d.y * m.y),
                           to_h(d.z * m.z), to_h(d.w * m.w)};
    size_t off = ((size_t)b * NN + q) * 1024 + n4;
    *(uint2*)&g_Af[off] = make_uint2((uint32_t)h[0] | ((uint32_t)h[1] << 16),
                                     (uint32_t)h[2] | ((uint32_t)h[3] << 16));
}

// ---------------------------------------------------------------------------
// kW: W -> single fp16, row f = k*64+o, col c.  Wr[f][c]=W[o*192+c*3+k]
// ---------------------------------------------------------------------------
__global__ void kW(const float* __restrict__ W) {
    int idx = blockIdx.x * 256 + threadIdx.x;
    if (idx >= NF * 16) return;
    int f = idx >> 4, c4 = (idx & 15) * 4;
    int k = f >> 6, o = f & 63;
    unsigned short h[4];
#pragma unroll
    for (int j = 0; j < 4; j++) h[j] = to_h(W[o * NF + (c4 + j) * 3 + k]);
    *(uint2*)&g_Wf[f * 64 + c4] = make_uint2((uint32_t)h[0] | ((uint32_t)h[1] << 16),
                                             (uint32_t)h[2] | ((uint32_t)h[3] << 16));
}

// ---------------------------------------------------------------------------
// K2 (mma): per CTA a 256-m strip; W resident (single fp16), x split hi/lo.
// z[f][m] = sum_c Wr[f][c]*x[b][c][m]; 2 MMA terms: W*Xh + W*Xl.
// k=0 -> g_z0 fp32; k>0 -> g_zf single fp16.
// ---------------------------------------------------------------------------
#define K2_W 0
#define K2_XBASE 27648
#define K2_XSTRIDE 18432          // per buffer: XH(9216) + XL(9216)
#define K2_SMEM 64512

__global__ __launch_bounds__(256, 2) void k2_mma(const float* __restrict__ x) {
    extern __shared__ __align__(128) char smem[];
    const uint32_t sb = smem_u32(smem);
    const int t = threadIdx.x, lane = t & 31, wid = t >> 5;
    const int mT = blockIdx.x * 256, b = blockIdx.y;

#pragma unroll
    for (int i = 0; i < 6; i++) {
        int idx = t + i * 256, r = idx >> 3, sg8 = idx & 7;
        cp16(sb + K2_W + r * 144 + sg8 * 16, (const char*)g_Wf + r * 128 + sg8 * 16);
    }
    asm volatile("cp.async.commit_group;");
    asm volatile("cp.async.wait_group 0;" ::: "memory");

    const int warpM = wid >> 1, warpN = wid & 1;
    const int lr = lane & 7, seg = lane >> 3;
    const int group = lane >> 2, tig = lane & 3;

    const int sg = t & 15, cbase = t >> 4;
    const float* xb_ptr = x + (size_t)b * NC * 32768 + sg * 4;

    float4 xr[4];
#pragma unroll
    for (int i = 0; i < 4; i++)
        xr[i] = *(const float4*)(xb_ptr + ((size_t)(cbase + 16 * i)) * 32768 + mT);

    for (int sub = 0; sub < 4; sub++) {
        const uint32_t xbuf = sb + K2_XBASE + (sub & 1) * K2_XSTRIDE;
#pragma unroll
        for (int i = 0; i < 4; i++) {
            int c = cbase + 16 * i;
            unsigned short h[4], l[4];
            split_h(xr[i].x, h[0], l[0]); split_h(xr[i].y, h[1], l[1]);
            split_h(xr[i].z, h[2], l[2]); split_h(xr[i].w, h[3], l[3]);
            *(uint2*)(smem + (xbuf - sb) + c * 144 + sg * 8) =
                make_uint2((uint32_t)h[0] | ((uint32_t)h[1] << 16),
                           (uint32_t)h[2] | ((uint32_t)h[3] << 16));
            *(uint2*)(smem + (xbuf - sb) + 9216 + c * 144 + sg * 8) =
                make_uint2((uint32_t)l[0] | ((uint32_t)l[1] << 16),
                           (uint32_t)l[2] | ((uint32_t)l[3] << 16));
        }
        __syncthreads();
        if (sub < 3) {
#pragma unroll
            for (int i = 0; i < 4; i++)
                xr[i] = *(const float4*)(xb_ptr + ((size_t)(cbase + 16 * i)) * 32768 +
                                         mT + (sub + 1) * 64);
        }

        float d[3][4][4];
#pragma unroll
        for (int i = 0; i < 3; i++)
#pragma unroll
            for (int j = 0; j < 4; j++)
#pragma unroll
                for (int e = 0; e < 4; e++) d[i][j][e] = 0.f;

#pragma unroll
        for (int s = 0; s < 4; s++) {
            uint32_t a[3][4], bh[4][2], bl[4][2];
#pragma unroll
            for (int mf = 0; mf < 3; mf++) {
                uint32_t row = warpM * 48 + mf * 16 + lr + (seg & 1) * 8;
                uint32_t col = (seg >> 1) * 16 + s * 32;
                ldm4(sb + K2_W + row * 144 + col, a[mf]);
            }
#pragma unroll
            for (int g = 0; g < 2; g++) {
                uint32_t row = s * 16 + lr + (seg & 1) * 8;
                uint32_t col = warpN * 64 + g * 32 + (seg >> 1) * 16;
                uint32_t r4[4];
                ldm4t(xbuf + row * 144 + col, r4);
                bh[g * 2][0] = r4[0]; bh[g * 2][1] = r4[1];
                bh[g * 2 + 1][0] = r4[2]; bh[g * 2 + 1][1] = r4[3];
                ldm4t(xbuf + 9216 + row * 144 + col, r4);
                bl[g * 2][0] = r4[0]; bl[g * 2][1] = r4[1];
                bl[g * 2 + 1][0] = r4[2]; bl[g * 2 + 1][1] = r4[3];
            }
#pragma unroll
            for (int mf = 0; mf < 3; mf++)
#pragma unroll
                for (int nf = 0; nf < 4; nf++) {
                    mma16816(d[mf][nf], a[mf], bh[nf]);
                    mma16816(d[mf][nf], a[mf], bl[nf]);
                }
        }

        const int m0 = mT + sub * 64;
#pragma unroll
        for (int mf = 0; mf < 3; mf++)
#pragma unroll
            for (int half = 0; half < 2; half++) {
                int f = warpM * 48 + mf * 16 + group + half * 8;
                int k = f >> 6, o = f & 63;
#pragma unroll
                for (int nf = 0; nf < 4; nf++) {
                    int m = m0 + warpN * 32 + nf * 8 + tig * 2;
                    float c0 = d[mf][nf][half * 2], c1 = d[mf][nf][half * 2 + 1];
                    if (k == 0) {
                        *(float2*)&g_z0[(size_t)(b * 64 + o) * 32768 + m] =
                            make_float2(c0, c1);
                    } else {
                        size_t off = (size_t)((b * 2 + k - 1) * 64 + o) * 32768 + m;
                        *(uint32_t*)&g_zf[off] =
                            (uint32_t)to_h(c0) | ((uint32_t)to_h(c1) << 16);
                    }
                }
            }
    }
}

// ---------------------------------------------------------------------------
// K3: fp16 mma GEMM, SINGLE term (A*B).  CTA 128(q) x 128(col), K=1024 in
// 32-n chunks, 3-stage cp.async ring.
// ---------------------------------------------------------------------------
#define OFF_A 0
#define OFF_B 10240
#define STAGEB 18944              // A 128x80 + B 32x272
#define SMEM_K3 (3 * STAGEB)

__device__ __forceinline__ void k3_load(uint32_t sb, int b, int q0, int o0,
                                        int stg, int kk) {
    const int t = threadIdx.x;
    const uint32_t st = sb + stg * STAGEB;
    const int kp = kk >> 4, n0 = (kk & 15) * 32;
    // A: 128 q-rows x 64B (32 k halves), pad 80
#pragma unroll
    for (int i = 0; i < 2; i++) {
        int idx = t + i * 256;
        int r = idx >> 2, u = (idx & 3) * 16;
        cp16(st + OFF_A + r * 80 + u,
             (const char*)g_Af + ((size_t)(b * NN + q0 + r)) * 2048 + kk * 64 + u);
    }
    // B: 32 n-rows x 256B (2o x 64l halves), pad 272
#pragma unroll
    for (int i = 0; i < 2; i++) {
        int idx = t + i * 256, nl = idx >> 4, sg = idx & 15;
        int ol = sg >> 3, l16 = (sg & 7) * 16;
        size_t src = ((size_t)((b * 2 + kp) * 64 + o0 + ol) * 512 + n0 + nl) * 128 + l16;
        cp16(st + OFF_B + nl * 272 + sg * 16, (const char*)g_zf + src);
    }
}

__global__ __launch_bounds__(256, 2) void k3_main(const float* __restrict__ ds,
                                                  const float* __restrict__ bias,
                                                  float* __restrict__ out) {
    extern __shared__ __align__(128) char smem[];
    const uint32_t sb = smem_u32(smem);
    const int t = threadIdx.x, lane = t & 31, wid = t >> 5;
    const int q0 = blockIdx.x * 128, colT = blockIdx.y * 128, b = blockIdx.z;
    const int o0 = blockIdx.y * 2;
    const int warpM = wid >> 2, warpN = wid & 3;
    const int lr = lane & 7, seg = lane >> 3;

    float d[4][4][4];
#pragma unroll
    for (int m = 0; m < 4; m++)
#pragma unroll
        for (int n = 0; n < 4; n++)
#pragma unroll
            for (int e = 0; e < 4; e++) d[m][n][e] = 0.f;

    k3_load(sb, b, q0, o0, 0, 0);
    asm volatile("cp.async.commit_group;");
    k3_load(sb, b, q0, o0, 1, 1);
    asm volatile("cp.async.commit_group;");
    k3_load(sb, b, q0, o0, 2, 2);
    asm volatile("cp.async.commit_group;");

    int cur = 0;
    for (int kk = 0; kk < 32; kk++) {
        if (kk < 30)       asm volatile("cp.async.wait_group 2;" ::: "memory");
        else if (kk == 30) asm volatile("cp.async.wait_group 1;" ::: "memory");
        else               asm volatile("cp.async.wait_group 0;" ::: "memory");
        __syncthreads();
        const uint32_t st = sb + cur * STAGEB;
#pragma unroll
        for (int s = 0; s < 2; s++) {
            uint32_t bh[4][2], a[4][4];
#pragma unroll
            for (int g = 0; g < 2; g++) {
                uint32_t row = s * 16 + lr + (seg & 1) * 8;
                uint32_t col = warpN * 64 + g * 32 + (seg >> 1) * 16;
                uint32_t r4[4];
                ldm4t(st + OFF_B + row * 272 + col, r4);
                bh[g * 2][0] = r4[0]; bh[g * 2][1] = r4[1];
                bh[g * 2 + 1][0] = r4[2]; bh[g * 2 + 1][1] = r4[3];
            }
#pragma unroll
            for (int mf = 0; mf < 4; mf++) {
                uint32_t row = warpM * 64 + mf * 16 + lr + (seg & 1) * 8;
                ldm4(st + OFF_A + row * 80 + (seg >> 1) * 16 + s * 32, a[mf]);
            }
#pragma unroll
            for (int mf = 0; mf < 4; mf++)
#pragma unroll
                for (int nf = 0; nf < 4; nf++)
                    mma16816(d[mf][nf], a[mf], bh[nf]);
        }
        __syncthreads();
        if (kk < 29) {
            k3_load(sb, b, q0, o0, cur, kk + 3);
            asm volatile("cp.async.commit_group;");
        }
        cur = (cur == 2) ? 0 : cur + 1;
    }

    // Epilogue: + bias + ds[q,q]*z0
    const int group = lane >> 2, tig = lane & 3;
#pragma unroll
    for (int mf = 0; mf < 4; mf++)
#pragma unroll
        for (int half = 0; half < 2; half++) {
            const int q = q0 + warpM * 64 + mf * 16 + group + half * 8;
            const float dqq = ds[((size_t)b * NN + q) * NN + q];
#pragma unroll
            for (int nf = 0; nf < 4; nf++) {
                const int colg = colT + warpN * 32 + nf * 8 + tig * 2;
                const int o = colg >> 6, l = colg & 63;
                const float bo = bias[o];
                float2 z0 = *(const float2*)&g_z0[(size_t)(b * 64 + o) * 32768 +
                                                  (size_t)q * 64 + l];
                float2 r;
                r.x = fmaf(dqq, z0.x, d[mf][nf][half * 2 + 0] + bo);
                r.y = fmaf(dqq, z0.y, d[mf][nf][half * 2 + 1] + bo);
                *(float2*)&out[(((size_t)(b * NC + o)) * NN + q) * 64 + l] = r;
            }
        }
}

// ---------------------------------------------------------------------------
extern "C" void kernel_launch(void* const* d_in, const int* in_sizes, int n_in,
                              void* d_out, int out_size) {
    const float* x    = (const float*)d_in[0];
    const float* adj  = (const float*)d_in[1];
    const float* ds   = (const float*)d_in[2];
    const float* W    = (const float*)d_in[3];
    const float* bias = (const float*)d_in[4];
    float* out = (float*)d_out;

    cudaFuncSetAttribute(k2_mma, cudaFuncAttributeMaxDynamicSharedMemorySize, K2_SMEM);
    cudaFuncSetAttribute(k3_main, cudaFuncAttributeMaxDynamicSharedMemorySize, SMEM_K3);

    k1_T2<<<dim3(32, 32), dim3(16, 16)>>>(adj);
    kA<<<dim3(512, 32), 256>>>(ds, adj);
    kW<<<12, 256>>>(W);
    k2_mma<<<dim3(128, 32), 256, K2_SMEM>>>(x);
    k3_main<<<dim3(4, 32, 32), 256, SMEM_K3>>>(ds, bias, out);
}

// round 12
// speedup vs baseline: 8.5774x; 1.0809x over previous
#include <cuda_runtime.h>
#include <cuda_fp16.h>
#include <cstdint>
#include <cstddef>

#define NB 32
#define NN 512
#define NL 64
#define NC 64
#define NF 192

// ---------------- scratch ----------------
__device__ float g_T2[NN * NN];
__device__ __half g_z0h[(size_t)NB * 64 * NN * NL];        // [b][o][n][l] fp16 (k=0 term)
__device__ __half g_zf[(size_t)NB * 2 * 64 * NN * NL];     // [b][kp][o][n][l] fp16
__device__ __half g_Af[(size_t)NB * NN * 1024];            // [b][q][n'] fp16
__device__ __half g_Wf[NF * 64];                           // [f=k*64+o][c] fp16

// ---------------- helpers ----------------
__device__ __forceinline__ uint32_t smem_u32(const void* p) {
    uint32_t a;
    asm("{ .reg .u64 t; cvta.to.shared.u64 t, %1; cvt.u32.u64 %0, t; }" : "=r"(a) : "l"(p));
    return a;
}
__device__ __forceinline__ void cp16(uint32_t dst, const void* src) {
    asm volatile("cp.async.cg.shared.global [%0], [%1], 16;" :: "r"(dst), "l"(src));
}
__device__ __forceinline__ unsigned short to_h(float v) {
    __half hb = __float2half_rn(v);
    return *reinterpret_cast<unsigned short*>(&hb);
}
__device__ __forceinline__ void ldm4(uint32_t addr, uint32_t* r) {
    asm volatile("ldmatrix.sync.aligned.m8n8.x4.shared.b16 {%0,%1,%2,%3}, [%4];"
                 : "=r"(r[0]), "=r"(r[1]), "=r"(r[2]), "=r"(r[3]) : "r"(addr));
}
__device__ __forceinline__ void ldm4t(uint32_t addr, uint32_t* r) {
    asm volatile("ldmatrix.sync.aligned.m8n8.x4.trans.shared.b16 {%0,%1,%2,%3}, [%4];"
                 : "=r"(r[0]), "=r"(r[1]), "=r"(r[2]), "=r"(r[3]) : "r"(addr));
}
__device__ __forceinline__ void mma16816(float* d, const uint32_t* a, const uint32_t* b) {
    asm volatile(
        "mma.sync.aligned.m16n8k16.row.col.f32.f16.f16.f32 "
        "{%0,%1,%2,%3}, {%4,%5,%6,%7}, {%8,%9}, {%0,%1,%2,%3};"
        : "+f"(d[0]), "+f"(d[1]), "+f"(d[2]), "+f"(d[3])
        : "r"(a[0]), "r"(a[1]), "r"(a[2]), "r"(a[3]), "r"(b[0]), "r"(b[1]));
}

// ---------------------------------------------------------------------------
// K1: T2 = 2*adj@adj - I
// ---------------------------------------------------------------------------
__global__ void k1_T2(const float* __restrict__ adj) {
    __shared__ float As[16][16];
    __shared__ float Bs[16][17];
    const int tx = threadIdx.x, ty = threadIdx.y;
    const int q = blockIdx.y * 16 + ty;
    const int n = blockIdx.x * 16 + tx;
    float acc = 0.f;
    for (int t0 = 0; t0 < NN; t0 += 16) {
        As[ty][tx] = adj[(size_t)q * NN + t0 + tx];
        Bs[ty][tx] = adj[(size_t)(t0 + ty) * NN + n];
        __syncthreads();
#pragma unroll
        for (int j = 0; j < 16; j++) acc = fmaf(As[ty][j], Bs[j][tx], acc);
        __syncthreads();
    }
    g_T2[(size_t)q * NN + n] = 2.f * acc - (q == n ? 1.f : 0.f);
}

// ---------------------------------------------------------------------------
// kA: A[b][q][n'] = ds[b][q][n]*(n'<512 ? adj : T2)[q][n] -> fp16
// ---------------------------------------------------------------------------
__global__ __launch_bounds__(256) void kA(const float* __restrict__ ds,
                                          const float* __restrict__ adj) {
    const int q = blockIdx.x, b = blockIdx.y, t = threadIdx.x;
    const int n4 = t * 4, n = n4 & 511;
    const float* mrow = (n4 < 512 ? adj : g_T2) + (size_t)q * NN + n;
    float4 m = *(const float4*)mrow;
    float4 d = *(const float4*)(ds + ((size_t)b * NN + q) * NN + n);
    unsigned short h[4] = {to_h(d.x * m.x), to_h(d.y * m.y),
                           to_h(d.z * m.z), to_h(d.w * m.w)};
    size_t off = ((size_t)b * NN + q) * 1024 + n4;
    *(uint2*)&g_Af[off] = make_uint2((uint32_t)h[0] | ((uint32_t)h[1] << 16),
                                     (uint32_t)h[2] | ((uint32_t)h[3] << 16));
}

// ---------------------------------------------------------------------------
// kW: W -> fp16, row f = k*64+o, col c.  Wr[f][c]=W[o*192+c*3+k]
// ---------------------------------------------------------------------------
__global__ void kW(const float* __restrict__ W) {
    int idx = blockIdx.x * 256 + threadIdx.x;
    if (idx >= NF * 16) return;
    int f = idx >> 4, c4 = (idx & 15) * 4;
    int k = f >> 6, o = f & 63;
    unsigned short h[4];
#pragma unroll
    for (int j = 0; j < 4; j++) h[j] = to_h(W[o * NF + (c4 + j) * 3 + k]);
    *(uint2*)&g_Wf[f * 64 + c4] = make_uint2((uint32_t)h[0] | ((uint32_t)h[1] << 16),
                                             (uint32_t)h[2] | ((uint32_t)h[3] << 16));
}

// ---------------------------------------------------------------------------
// K2 (mma): per CTA a 256-m strip; W resident, x single fp16 (1 MMA term).
// z[f][m] = sum_c Wr[f][c]*x[b][c][m]; k=0 -> g_z0h fp16; k>0 -> g_zf fp16.
// ---------------------------------------------------------------------------
#define K2_W 0
#define K2_XBASE 27648
#define K2_XSTRIDE 9216           // per buffer: X (64 rows x 144B)
#define K2_SMEM 46080

__global__ __launch_bounds__(256, 2) void k2_mma(const float* __restrict__ x) {
    extern __shared__ __align__(128) char smem[];
    const uint32_t sb = smem_u32(smem);
    const int t = threadIdx.x, lane = t & 31, wid = t >> 5;
    const int mT = blockIdx.x * 256, b = blockIdx.y;

#pragma unroll
    for (int i = 0; i < 6; i++) {
        int idx = t + i * 256, r = idx >> 3, sg8 = idx & 7;
        cp16(sb + K2_W + r * 144 + sg8 * 16, (const char*)g_Wf + r * 128 + sg8 * 16);
    }
    asm volatile("cp.async.commit_group;");
    asm volatile("cp.async.wait_group 0;" ::: "memory");

    const int warpM = wid >> 1, warpN = wid & 1;
    const int lr = lane & 7, seg = lane >> 3;
    const int group = lane >> 2, tig = lane & 3;

    const int sg = t & 15, cbase = t >> 4;
    const float* xb_ptr = x + (size_t)b * NC * 32768 + sg * 4;

    float4 xr[4];
#pragma unroll
    for (int i = 0; i < 4; i++)
        xr[i] = *(const float4*)(xb_ptr + ((size_t)(cbase + 16 * i)) * 32768 + mT);

    for (int sub = 0; sub < 4; sub++) {
        const uint32_t xbuf = sb + K2_XBASE + (sub & 1) * K2_XSTRIDE;
#pragma unroll
        for (int i = 0; i < 4; i++) {
            int c = cbase + 16 * i;
            unsigned short h[4] = {to_h(xr[i].x), to_h(xr[i].y),
                                   to_h(xr[i].z), to_h(xr[i].w)};
            *(uint2*)(smem + (xbuf - sb) + c * 144 + sg * 8) =
                make_uint2((uint32_t)h[0] | ((uint32_t)h[1] << 16),
                           (uint32_t)h[2] | ((uint32_t)h[3] << 16));
        }
        __syncthreads();
        if (sub < 3) {
#pragma unroll
            for (int i = 0; i < 4; i++)
                xr[i] = *(const float4*)(xb_ptr + ((size_t)(cbase + 16 * i)) * 32768 +
                                         mT + (sub + 1) * 64);
        }

        float d[3][4][4];
#pragma unroll
        for (int i = 0; i < 3; i++)
#pragma unroll
            for (int j = 0; j < 4; j++)
#pragma unroll
                for (int e = 0; e < 4; e++) d[i][j][e] = 0.f;

#pragma unroll
        for (int s = 0; s < 4; s++) {
            uint32_t a[3][4], bh[4][2];
#pragma unroll
            for (int mf = 0; mf < 3; mf++) {
                uint32_t row = warpM * 48 + mf * 16 + lr + (seg & 1) * 8;
                uint32_t col = (seg >> 1) * 16 + s * 32;
                ldm4(sb + K2_W + row * 144 + col, a[mf]);
            }
#pragma unroll
            for (int g = 0; g < 2; g++) {
                uint32_t row = s * 16 + lr + (seg & 1) * 8;
                uint32_t col = warpN * 64 + g * 32 + (seg >> 1) * 16;
                uint32_t r4[4];
                ldm4t(xbuf + row * 144 + col, r4);
                bh[g * 2][0] = r4[0]; bh[g * 2][1] = r4[1];
                bh[g * 2 + 1][0] = r4[2]; bh[g * 2 + 1][1] = r4[3];
            }
#pragma unroll
            for (int mf = 0; mf < 3; mf++)
#pragma unroll
                for (int nf = 0; nf < 4; nf++)
                    mma16816(d[mf][nf], a[mf], bh[nf]);
        }

        const int m0 = mT + sub * 64;
#pragma unroll
        for (int mf = 0; mf < 3; mf++)
#pragma unroll
            for (int half = 0; half < 2; half++) {
                int f = warpM * 48 + mf * 16 + group + half * 8;
                int k = f >> 6, o = f & 63;
#pragma unroll
                for (int nf = 0; nf < 4; nf++) {
                    int m = m0 + warpN * 32 + nf * 8 + tig * 2;
                    float c0 = d[mf][nf][half * 2], c1 = d[mf][nf][half * 2 + 1];
                    uint32_t pk = (uint32_t)to_h(c0) | ((uint32_t)to_h(c1) << 16);
                    if (k == 0) {
                        *(uint32_t*)&g_z0h[(size_t)(b * 64 + o) * 32768 + m] = pk;
                    } else {
                        *(uint32_t*)&g_zf[(size_t)((b * 2 + k - 1) * 64 + o) * 32768 + m] = pk;
                    }
                }
            }
    }
}

// ---------------------------------------------------------------------------
// K3: fp16 mma GEMM, single term.  CTA 128(q) x 128(col), K=1024 in 32-n
// chunks, 3-stage cp.async ring.
// ---------------------------------------------------------------------------
#define OFF_A 0
#define OFF_B 10240
#define STAGEB 18944              // A 128x80 + B 32x272
#define SMEM_K3 (3 * STAGEB)

__device__ __forceinline__ void k3_load(uint32_t sb, int b, int q0, int o0,
                                        int stg, int kk) {
    const int t = threadIdx.x;
    const uint32_t st = sb + stg * STAGEB;
    const int kp = kk >> 4, n0 = (kk & 15) * 32;
#pragma unroll
    for (int i = 0; i < 2; i++) {
        int idx = t + i * 256;
        int r = idx >> 2, u = (idx & 3) * 16;
        cp16(st + OFF_A + r * 80 + u,
             (const char*)g_Af + ((size_t)(b * NN + q0 + r)) * 2048 + kk * 64 + u);
    }
#pragma unroll
    for (int i = 0; i < 2; i++) {
        int idx = t + i * 256, nl = idx >> 4, sg = idx & 15;
        int ol = sg >> 3, l16 = (sg & 7) * 16;
        size_t src = ((size_t)((b * 2 + kp) * 64 + o0 + ol) * 512 + n0 + nl) * 128 + l16;
        cp16(st + OFF_B + nl * 272 + sg * 16, (const char*)g_zf + src);
    }
}

__global__ __launch_bounds__(256, 2) void k3_main(const float* __restrict__ ds,
                                                  const float* __restrict__ bias,
                                                  float* __restrict__ out) {
    extern __shared__ __align__(128) char smem[];
    const uint32_t sb = smem_u32(smem);
    const int t = threadIdx.x, lane = t & 31, wid = t >> 5;
    const int q0 = blockIdx.x * 128, colT = blockIdx.y * 128, b = blockIdx.z;
    const int o0 = blockIdx.y * 2;
    const int warpM = wid >> 2, warpN = wid & 3;
    const int lr = lane & 7, seg = lane >> 3;

    float d[4][4][4];
#pragma unroll
    for (int m = 0; m < 4; m++)
#pragma unroll
        for (int n = 0; n < 4; n++)
#pragma unroll
            for (int e = 0; e < 4; e++) d[m][n][e] = 0.f;

    k3_load(sb, b, q0, o0, 0, 0);
    asm volatile("cp.async.commit_group;");
    k3_load(sb, b, q0, o0, 1, 1);
    asm volatile("cp.async.commit_group;");
    k3_load(sb, b, q0, o0, 2, 2);
    asm volatile("cp.async.commit_group;");

    int cur = 0;
    for (int kk = 0; kk < 32; kk++) {
        if (kk < 30)       asm volatile("cp.async.wait_group 2;" ::: "memory");
        else if (kk == 30) asm volatile("cp.async.wait_group 1;" ::: "memory");
        else               asm volatile("cp.async.wait_group 0;" ::: "memory");
        __syncthreads();
        const uint32_t st = sb + cur * STAGEB;
#pragma unroll
        for (int s = 0; s < 2; s++) {
            uint32_t bh[4][2], a[4][4];
#pragma unroll
            for (int g = 0; g < 2; g++) {
                uint32_t row = s * 16 + lr + (seg & 1) * 8;
                uint32_t col = warpN * 64 + g * 32 + (seg >> 1) * 16;
                uint32_t r4[4];
                ldm4t(st + OFF_B + row * 272 + col, r4);
                bh[g * 2][0] = r4[0]; bh[g * 2][1] = r4[1];
                bh[g * 2 + 1][0] = r4[2]; bh[g * 2 + 1][1] = r4[3];
            }
#pragma unroll
            for (int mf = 0; mf < 4; mf++) {
                uint32_t row = warpM * 64 + mf * 16 + lr + (seg & 1) * 8;
                ldm4(st + OFF_A + row * 80 + (seg >> 1) * 16 + s * 32, a[mf]);
            }
#pragma unroll
            for (int mf = 0; mf < 4; mf++)
#pragma unroll
                for (int nf = 0; nf < 4; nf++)
                    mma16816(d[mf][nf], a[mf], bh[nf]);
        }
        __syncthreads();
        if (kk < 29) {
            k3_load(sb, b, q0, o0, cur, kk + 3);
            asm volatile("cp.async.commit_group;");
        }
        cur = (cur == 2) ? 0 : cur + 1;
    }

    // Epilogue: + bias + ds[q,q]*z0
    const int group = lane >> 2, tig = lane & 3;
#pragma unroll
    for (int mf = 0; mf < 4; mf++)
#pragma unroll
        for (int half = 0; half < 2; half++) {
            const int q = q0 + warpM * 64 + mf * 16 + group + half * 8;
            const float dqq = ds[((size_t)b * NN + q) * NN + q];
#pragma unroll
            for (int nf = 0; nf < 4; nf++) {
                const int colg = colT + warpN * 32 + nf * 8 + tig * 2;
                const int o = colg >> 6, l = colg & 63;
                const float bo = bias[o];
                uint32_t zp = *(const uint32_t*)&g_z0h[(size_t)(b * 64 + o) * 32768 +
                                                       (size_t)q * 64 + l];
                float2 z0 = __half22float2(*reinterpret_cast<__half2*>(&zp));
                float2 r;
                r.x = fmaf(dqq, z0.x, d[mf][nf][half * 2 + 0] + bo);
                r.y = fmaf(dqq, z0.y, d[mf][nf][half * 2 + 1] + bo);
                *(float2*)&out[(((size_t)(b * NC + o)) * NN + q) * 64 + l] = r;
            }
        }
}

// ---------------------------------------------------------------------------
extern "C" void kernel_launch(void* const* d_in, const int* in_sizes, int n_in,
                              void* d_out, int out_size) {
    const float* x    = (const float*)d_in[0];
    const float* adj  = (const float*)d_in[1];
    const float* ds   = (const float*)d_in[2];
    const float* W    = (const float*)d_in[3];
    const float* bias = (const float*)d_in[4];
    float* out = (float*)d_out;

    cudaFuncSetAttribute(k2_mma, cudaFuncAttributeMaxDynamicSharedMemorySize, K2_SMEM);
    cudaFuncSetAttribute(k3_main, cudaFuncAttributeMaxDynamicSharedMemorySize, SMEM_K3);

    k1_T2<<<dim3(32, 32), dim3(16, 16)>>>(adj);
    kA<<<dim3(512, 32), 256>>>(ds, adj);
    kW<<<12, 256>>>(W);
    k2_mma<<<dim3(128, 32), 256, K2_SMEM>>>(x);
    k3_main<<<dim3(4, 32, 32), 256, SMEM_K3>>>(ds, bias, out);
}